// round 1
// baseline (speedup 1.0000x reference)
#include <cuda_runtime.h>
#include <math.h>

// Problem constants
constexpr int NV  = 65;
constexpr int ND  = 384;
constexpr int NH  = 6;
constexpr int NHD = 64;
constexpr int NL  = 6;
constexpr int NT  = 256;
constexpr int NB  = 64;
constexpr int MT  = NB * NT;      // 16384 rows
constexpr int ND4 = 4 * ND;       // 1536

// Scratch buffers (allocation-free: __device__ globals)
__device__ float g_x  [MT * ND];
__device__ float g_h  [MT * ND];
__device__ float g_q  [MT * ND];
__device__ float g_k  [MT * ND];
__device__ float g_v  [MT * ND];
__device__ float g_att[MT * ND];
__device__ float g_hid[MT * ND4];

// ---------------------------------------------------------------------------
// Embedding: x[m, d] = tok_emb[idx[m], d] + pos_emb[m % T, d]
// ---------------------------------------------------------------------------
__global__ void embed_kernel(const int* __restrict__ idx,
                             const float* __restrict__ tok,
                             const float* __restrict__ pos,
                             float* __restrict__ out)
{
    int gid = blockIdx.x * blockDim.x + threadIdx.x;
    int m = gid / ND, d = gid - m * ND;
    int token = idx[m];
    out[gid] = tok[(size_t)token * ND + d] + pos[(m % NT) * ND + d];
}

// ---------------------------------------------------------------------------
// LayerNorm over last dim (384), eps = 1e-3. One block (128 thr) per row.
// ---------------------------------------------------------------------------
__global__ __launch_bounds__(128) void ln_kernel(const float* __restrict__ x,
                                                 const float* __restrict__ g,
                                                 const float* __restrict__ bb,
                                                 float* __restrict__ out)
{
    int row = blockIdx.x;
    int tid = threadIdx.x;
    const float* xr = x + (size_t)row * ND;

    float xv[3];
    float s1 = 0.f, s2 = 0.f;
#pragma unroll
    for (int j = 0; j < 3; j++) {
        float v = xr[tid + j * 128];
        xv[j] = v; s1 += v; s2 += v * v;
    }
#pragma unroll
    for (int o = 16; o > 0; o >>= 1) {
        s1 += __shfl_down_sync(0xFFFFFFFFu, s1, o);
        s2 += __shfl_down_sync(0xFFFFFFFFu, s2, o);
    }
    __shared__ float sh1[4], sh2[4];
    int w = tid >> 5;
    if ((tid & 31) == 0) { sh1[w] = s1; sh2[w] = s2; }
    __syncthreads();
    s1 = sh1[0] + sh1[1] + sh1[2] + sh1[3];
    s2 = sh2[0] + sh2[1] + sh2[2] + sh2[3];

    float mean = s1 * (1.f / ND);
    float var  = s2 * (1.f / ND) - mean * mean;
    float rstd = rsqrtf(var + 1e-3f);
#pragma unroll
    for (int j = 0; j < 3; j++) {
        int c = tid + j * 128;
        out[(size_t)row * ND + c] = (xv[j] - mean) * rstd * g[c] + bb[c];
    }
}

// ---------------------------------------------------------------------------
// Generic tiled SGEMM: C[m,c] = sum_k A[m,k] * B(k,c)  (+bias)(+relu)(+resid)
// B addressing: off = (c/colBlock)*blockStride + k*colBlock + (c%colBlock)
//   plain row-major [K,N] : colBlock=N,  blockStride=0
//   head-blocked (H,D,HD) : colBlock=HD, blockStride=D*HD
// Tile: 64x64x16, 256 threads, 4x4 micro-tile.
// M and K must be multiples of 64/16 (true here); N may be ragged (head: 65).
// ---------------------------------------------------------------------------
template <bool RELU, bool RESID>
__global__ __launch_bounds__(256) void gemm_kernel(
    const float* __restrict__ A, const float* __restrict__ Bm,
    const float* __restrict__ bias, const float* __restrict__ resid,
    float* __restrict__ Cout, int N, int K, int colBlock, int blockStride)
{
    __shared__ float sA[16][65];
    __shared__ float sB[16][64];

    int tid  = threadIdx.x;
    int row0 = blockIdx.y * 64;
    int col0 = blockIdx.x * 64;
    int tx = tid & 15, ty = tid >> 4;

    int am = tid >> 2;          // 0..63 (A row within tile)
    int ak = (tid & 3) * 4;     // 0,4,8,12
    int bk = tid >> 4;          // 0..15 (B k within tile)
    int bc = (tid & 15) * 4;    // 0..60

    float acc[4][4] = {};

    for (int k0 = 0; k0 < K; k0 += 16) {
        float4 av = *(const float4*)(A + (size_t)(row0 + am) * K + k0 + ak);
        sA[ak + 0][am] = av.x; sA[ak + 1][am] = av.y;
        sA[ak + 2][am] = av.z; sA[ak + 3][am] = av.w;
#pragma unroll
        for (int j = 0; j < 4; j++) {
            int c = col0 + bc + j;
            float vb = 0.f;
            if (c < N) {
                size_t off = (size_t)(c / colBlock) * blockStride
                           + (size_t)(k0 + bk) * colBlock + (c % colBlock);
                vb = Bm[off];
            }
            sB[bk][bc + j] = vb;
        }
        __syncthreads();
#pragma unroll
        for (int kk = 0; kk < 16; kk++) {
            float a[4], b[4];
#pragma unroll
            for (int i = 0; i < 4; i++) a[i] = sA[kk][ty * 4 + i];
            float4 bv = *(const float4*)&sB[kk][tx * 4];
            b[0] = bv.x; b[1] = bv.y; b[2] = bv.z; b[3] = bv.w;
#pragma unroll
            for (int i = 0; i < 4; i++)
#pragma unroll
                for (int j = 0; j < 4; j++) acc[i][j] += a[i] * b[j];
        }
        __syncthreads();
    }

#pragma unroll
    for (int i = 0; i < 4; i++) {
        int r = row0 + ty * 4 + i;
#pragma unroll
        for (int j = 0; j < 4; j++) {
            int c = col0 + tx * 4 + j;
            if (c < N) {
                float vv = acc[i][j];
                if (bias) vv += bias[c];
                if (RELU) vv = fmaxf(vv, 0.f);
                if (RESID) vv += resid[(size_t)r * N + c];
                Cout[(size_t)r * N + c] = vv;
            }
        }
    }
}

// ---------------------------------------------------------------------------
// Fused causal attention. One block per (b,h); thread t = query row t.
// q/k/v/out layout: [B, T, H, HD] (row index m = b*T+t, col = h*HD+d).
// Online softmax; scale = D^-0.5 (full embed dim, per reference).
// ---------------------------------------------------------------------------
__global__ __launch_bounds__(256) void attn_kernel(const float* __restrict__ q,
                                                   const float* __restrict__ k,
                                                   const float* __restrict__ v,
                                                   float* __restrict__ out)
{
    __shared__ float Ks[64][64];
    __shared__ float Vs[64][64];

    int bh = blockIdx.x;
    int b = bh / NH, h = bh - b * NH;
    int t = threadIdx.x;

    const float scale = rsqrtf((float)ND);
    size_t qbase = ((size_t)(b * NT + t) * NH + h) * NHD;

    float qr[NHD];
#pragma unroll
    for (int d = 0; d < NHD; d++) qr[d] = q[qbase + d] * scale;

    float o[NHD];
#pragma unroll
    for (int d = 0; d < NHD; d++) o[d] = 0.f;
    float mval = -1e30f, lsum = 0.f;

    for (int s0 = 0; s0 < NT; s0 += 64) {
        __syncthreads();
#pragma unroll
        for (int i = 0; i < 16; i++) {
            int e = threadIdx.x + i * 256;
            int r = e >> 6, c = e & 63;
            size_t kb = ((size_t)(b * NT + s0 + r) * NH + h) * NHD + c;
            Ks[r][c] = k[kb];
            Vs[r][c] = v[kb];
        }
        __syncthreads();
        if (t >= s0) {
            int send = min(63, t - s0);
            for (int sr = 0; sr <= send; sr++) {
                float sc = 0.f;
#pragma unroll
                for (int d = 0; d < NHD; d++) sc += qr[d] * Ks[sr][d];
                float nm   = fmaxf(mval, sc);
                float corr = __expf(mval - nm);
                float p    = __expf(sc - nm);
                lsum = lsum * corr + p;
#pragma unroll
                for (int d = 0; d < NHD; d++) o[d] = o[d] * corr + p * Vs[sr][d];
                mval = nm;
            }
        }
    }
    float inv = 1.f / lsum;
#pragma unroll
    for (int d = 0; d < NHD; d++) out[qbase + d] = o[d] * inv;
}

// ---------------------------------------------------------------------------
extern "C" void kernel_launch(void* const* d_in, const int* in_sizes, int n_in,
                              void* d_out, int out_size)
{
    const int*   idx   = (const int*)  d_in[0];
    const float* tok   = (const float*)d_in[1];
    const float* pos   = (const float*)d_in[2];
    const float* Wq    = (const float*)d_in[3];
    const float* Wk    = (const float*)d_in[4];
    const float* Wv    = (const float*)d_in[5];
    const float* Wproj = (const float*)d_in[6];
    const float* bproj = (const float*)d_in[7];
    const float* W1    = (const float*)d_in[8];
    const float* b1    = (const float*)d_in[9];
    const float* W2    = (const float*)d_in[10];
    const float* b2    = (const float*)d_in[11];
    const float* ln1g  = (const float*)d_in[12];
    const float* ln1b  = (const float*)d_in[13];
    const float* ln2g  = (const float*)d_in[14];
    const float* ln2b  = (const float*)d_in[15];
    const float* lnfg  = (const float*)d_in[16];
    const float* lnfb  = (const float*)d_in[17];
    const float* Whead = (const float*)d_in[18];
    const float* bhead = (const float*)d_in[19];
    float* out = (float*)d_out;

    float *px, *ph, *pq, *pk, *pv, *pa, *pm;
    cudaGetSymbolAddress((void**)&px, g_x);
    cudaGetSymbolAddress((void**)&ph, g_h);
    cudaGetSymbolAddress((void**)&pq, g_q);
    cudaGetSymbolAddress((void**)&pk, g_k);
    cudaGetSymbolAddress((void**)&pv, g_v);
    cudaGetSymbolAddress((void**)&pa, g_att);
    cudaGetSymbolAddress((void**)&pm, g_hid);

    embed_kernel<<<(MT * ND) / 256, 256>>>(idx, tok, pos, px);

    dim3 gD((ND + 63) / 64, MT / 64);    // N=384 gemms
    dim3 g4((ND4 + 63) / 64, MT / 64);   // N=1536 gemm
    dim3 gH((NV + 63) / 64, MT / 64);    // head gemm

    const int headBS = ND * NHD;         // 24576: per-head block stride in Wq/Wk/Wv

    for (int l = 0; l < NL; l++) {
        ln_kernel<<<MT, 128>>>(px, ln1g + l * ND, ln1b + l * ND, ph);

        const size_t wOff = (size_t)l * NH * ND * NHD;
        gemm_kernel<false, false><<<gD, 256>>>(ph, Wq + wOff, nullptr, nullptr,
                                               pq, ND, ND, NHD, headBS);
        gemm_kernel<false, false><<<gD, 256>>>(ph, Wk + wOff, nullptr, nullptr,
                                               pk, ND, ND, NHD, headBS);
        gemm_kernel<false, false><<<gD, 256>>>(ph, Wv + wOff, nullptr, nullptr,
                                               pv, ND, ND, NHD, headBS);

        attn_kernel<<<NB * NH, 256>>>(pq, pk, pv, pa);

        gemm_kernel<false, true><<<gD, 256>>>(pa, Wproj + (size_t)l * ND * ND,
                                              bproj + l * ND, px, px,
                                              ND, ND, ND, 0);

        ln_kernel<<<MT, 128>>>(px, ln2g + l * ND, ln2b + l * ND, ph);

        gemm_kernel<true, false><<<g4, 256>>>(ph, W1 + (size_t)l * ND * ND4,
                                              b1 + l * ND4, nullptr, pm,
                                              ND4, ND, ND4, 0);
        gemm_kernel<false, true><<<gD, 256>>>(pm, W2 + (size_t)l * ND4 * ND,
                                              b2 + l * ND, px, px,
                                              ND, ND4, ND, 0);
    }

    ln_kernel<<<MT, 128>>>(px, lnfg, lnfb, ph);
    gemm_kernel<false, false><<<gH, 256>>>(ph, Whead, bhead, nullptr,
                                           out, NV, ND, NV, 0);
}

// round 3
// speedup vs baseline: 2.4368x; 2.4368x over previous
#include <cuda_runtime.h>
#include <cstdint>
#include <math.h>

// ---------------------------------------------------------------------------
// Problem constants
// ---------------------------------------------------------------------------
constexpr int NV  = 65;
constexpr int ND  = 384;
constexpr int NH  = 6;
constexpr int NHD = 64;
constexpr int NL  = 6;
constexpr int NT  = 256;
constexpr int NB  = 64;
constexpr int MT  = NB * NT;       // 16384
constexpr int ND4 = 4 * ND;        // 1536
constexpr int NQKV = 3 * ND;       // 1152

// ---------------------------------------------------------------------------
// Scratch (__device__ globals; allocation-free)
// ---------------------------------------------------------------------------
__device__ float g_x  [MT * ND];
__device__ float g_h  [MT * ND];
__device__ float g_qkv[MT * NQKV];
__device__ float g_att[MT * ND];
__device__ float g_hid[MT * ND4];

// Transposed (K-major, tf32-rounded) weights
constexpr size_t OFF_QKV  = 0;
constexpr size_t OFF_PROJ = OFF_QKV  + (size_t)NL * NQKV * ND;
constexpr size_t OFF_W1   = OFF_PROJ + (size_t)NL * ND * ND;
constexpr size_t OFF_W2   = OFF_W1   + (size_t)NL * ND4 * ND;
constexpr size_t OFF_HEAD = OFF_W2   + (size_t)NL * ND * ND4;
constexpr size_t WT_TOTAL = OFF_HEAD + (size_t)NV * ND;
__device__ float g_wT[WT_TOTAL];

// ---------------------------------------------------------------------------
// Helpers
// ---------------------------------------------------------------------------
__device__ __forceinline__ uint32_t smem_u32(const void* p) {
    uint32_t a;
    asm("{ .reg .u64 t; cvta.to.shared.u64 t, %1; cvt.u32.u64 %0, t; }"
        : "=r"(a) : "l"(p));
    return a;
}
__device__ __forceinline__ float tf32r(float x) {
    uint32_t o;
    asm("cvt.rna.tf32.f32 %0, %1;" : "=r"(o) : "f"(x));
    return __uint_as_float(o);
}
__device__ __forceinline__ uint32_t tf32b(float x) {
    uint32_t o;
    asm("cvt.rna.tf32.f32 %0, %1;" : "=r"(o) : "f"(x));
    return o;
}
__device__ __forceinline__ void cp16(uint32_t dst, const float* src, int srcsize) {
    asm volatile("cp.async.cg.shared.global [%0], [%1], 16, %2;"
                 :: "r"(dst), "l"(src), "r"(srcsize) : "memory");
}
__device__ __forceinline__ void cp_commit() {
    asm volatile("cp.async.commit_group;" ::: "memory");
}
__device__ __forceinline__ void mma_tf32(float* c, const uint32_t* a, const uint32_t* b) {
    asm volatile(
        "mma.sync.aligned.m16n8k8.row.col.f32.tf32.tf32.f32 "
        "{%0,%1,%2,%3}, {%4,%5,%6,%7}, {%8,%9}, {%0,%1,%2,%3};"
        : "+f"(c[0]), "+f"(c[1]), "+f"(c[2]), "+f"(c[3])
        : "r"(a[0]), "r"(a[1]), "r"(a[2]), "r"(a[3]), "r"(b[0]), "r"(b[1]));
}

// ---------------------------------------------------------------------------
// Embedding
// ---------------------------------------------------------------------------
__global__ void embed_kernel(const int* __restrict__ idx,
                             const float* __restrict__ tok,
                             const float* __restrict__ pos,
                             float* __restrict__ out)
{
    int gid = blockIdx.x * blockDim.x + threadIdx.x;
    int m = gid / ND, d = gid - m * ND;
    out[gid] = tok[(size_t)idx[m] * ND + d] + pos[(m % NT) * ND + d];
}

// ---------------------------------------------------------------------------
// LayerNorm (eps 1e-3), one 128-thread block per row of 384
// ---------------------------------------------------------------------------
__global__ __launch_bounds__(128) void ln_kernel(const float* __restrict__ x,
                                                 const float* __restrict__ g,
                                                 const float* __restrict__ bb,
                                                 float* __restrict__ out)
{
    int row = blockIdx.x, tid = threadIdx.x;
    const float* xr = x + (size_t)row * ND;
    float xv[3], s1 = 0.f, s2 = 0.f;
#pragma unroll
    for (int j = 0; j < 3; j++) {
        float v = xr[tid + j * 128];
        xv[j] = v; s1 += v; s2 += v * v;
    }
#pragma unroll
    for (int o = 16; o > 0; o >>= 1) {
        s1 += __shfl_down_sync(0xFFFFFFFFu, s1, o);
        s2 += __shfl_down_sync(0xFFFFFFFFu, s2, o);
    }
    __shared__ float sh1[4], sh2[4];
    int w = tid >> 5;
    if ((tid & 31) == 0) { sh1[w] = s1; sh2[w] = s2; }
    __syncthreads();
    s1 = sh1[0] + sh1[1] + sh1[2] + sh1[3];
    s2 = sh2[0] + sh2[1] + sh2[2] + sh2[3];
    float mean = s1 * (1.f / ND);
    float var  = s2 * (1.f / ND) - mean * mean;
    float rstd = rsqrtf(var + 1e-3f);
#pragma unroll
    for (int j = 0; j < 3; j++) {
        int c = tid + j * 128;
        out[(size_t)row * ND + c] = (xv[j] - mean) * rstd * g[c] + bb[c];
    }
}

// ---------------------------------------------------------------------------
// Weight transposes -> K-major [N, K], tf32 (round-to-nearest) pre-rounded
// ---------------------------------------------------------------------------
__global__ void qkvT_kernel(const float* __restrict__ Wq,
                            const float* __restrict__ Wk,
                            const float* __restrict__ Wv,
                            float* __restrict__ dst)
{
    int gid = blockIdx.x * blockDim.x + threadIdx.x;
    int d = gid % ND;
    int rest = gid / ND;
    int n = rest % NQKV;
    int l = rest / NQKV;
    int which = n / ND, nn = n % ND;
    int h = nn / NHD, hd = nn % NHD;
    const float* src = (which == 0) ? Wq : (which == 1) ? Wk : Wv;
    dst[gid] = tf32r(src[(((size_t)l * NH + h) * ND + d) * NHD + hd]);
}

__global__ void transT_kernel(const float* __restrict__ src,
                              float* __restrict__ dst, int Kd, int Nd)
{
    int gid = blockIdx.x * blockDim.x + threadIdx.x;
    int k = gid % Kd;
    int rest = gid / Kd;
    int n = rest % Nd;
    int l = rest / Nd;
    dst[gid] = tf32r(src[((size_t)l * Kd + k) * Nd + n]);
}

// ---------------------------------------------------------------------------
// tf32 mma.sync GEMM: C[M,N] = A[M,K] * B^T (B supplied [N,K] K-major)
// Tile 128x128x32; 8 warps (4M x 2N); warp tile 32x64 of m16n8k8.
// smem rows padded to 36 floats for conflict-free fragment loads.
// ---------------------------------------------------------------------------
constexpr int RS = 36;                       // padded row stride (floats)
constexpr int TILE_F = 128 * RS;             // floats per tile buffer
constexpr int SM_FLOATS = 4 * TILE_F;        // A0,A1,B0,B1
constexpr int SM_BYTES = SM_FLOATS * 4;      // 73728

template <bool RELU, bool RESID>
__global__ __launch_bounds__(256) void tc_gemm(
    const float* __restrict__ A, const float* __restrict__ B,
    const float* __restrict__ bias, const float* __restrict__ resid,
    float* __restrict__ C, int N, int K)
{
    extern __shared__ float smf[];
    const int tid = threadIdx.x;
    const int row0 = blockIdx.y * 128;
    const int col0 = blockIdx.x * 128;

    float* sA[2] = { smf, smf + TILE_F };
    float* sB[2] = { smf + 2 * TILE_F, smf + 3 * TILE_F };
    uint32_t sAu[2] = { smem_u32(sA[0]), smem_u32(sA[1]) };
    uint32_t sBu[2] = { smem_u32(sB[0]), smem_u32(sB[1]) };

    const int KT = K / 32;

    auto prefetch = [&](int kt, int bb) {
#pragma unroll
        for (int i = 0; i < 4; i++) {
            int slot = tid + i * 256;         // 0..1023
            int r = slot >> 3, c4 = slot & 7;
            // A tile: rows always valid (M multiple of 128)
            cp16(sAu[bb] + (uint32_t)(r * RS + c4 * 4) * 4,
                 A + (size_t)(row0 + r) * K + kt * 32 + c4 * 4, 16);
            // B tile: row n may exceed N (head gemm) -> zero-fill
            int n = col0 + r;
            const float* src = B + (size_t)(n < N ? n : N - 1) * K + kt * 32 + c4 * 4;
            cp16(sBu[bb] + (uint32_t)(r * RS + c4 * 4) * 4, src, n < N ? 16 : 0);
        }
        cp_commit();
    };

    const int w = tid >> 5, lane = tid & 31;
    const int g = lane >> 2, tg = lane & 3;
    const int wm = (w & 3) * 32;
    const int wn = (w >> 2) * 64;

    float acc[2][8][4];
#pragma unroll
    for (int i = 0; i < 2; i++)
#pragma unroll
        for (int j = 0; j < 8; j++)
#pragma unroll
            for (int q = 0; q < 4; q++) acc[i][j][q] = 0.f;

    prefetch(0, 0);
    if (KT > 1) prefetch(1, 1);

    for (int kt = 0; kt < KT; kt++) {
        if (kt == KT - 1) asm volatile("cp.async.wait_group 0;" ::: "memory");
        else              asm volatile("cp.async.wait_group 1;" ::: "memory");
        __syncthreads();

        const float* cA = sA[kt & 1];
        const float* cB = sB[kt & 1];
#pragma unroll
        for (int kk = 0; kk < 4; kk++) {
            const int k0 = kk * 8;
            uint32_t a[2][4];
#pragma unroll
            for (int i = 0; i < 2; i++) {
                int r = wm + 16 * i + g;
                a[i][0] = tf32b(cA[r * RS + k0 + tg]);
                a[i][1] = tf32b(cA[(r + 8) * RS + k0 + tg]);
                a[i][2] = tf32b(cA[r * RS + k0 + tg + 4]);
                a[i][3] = tf32b(cA[(r + 8) * RS + k0 + tg + 4]);
            }
            uint32_t b[8][2];
#pragma unroll
            for (int j = 0; j < 8; j++) {
                int n = wn + 8 * j + g;
                b[j][0] = __float_as_uint(cB[n * RS + k0 + tg]);
                b[j][1] = __float_as_uint(cB[n * RS + k0 + tg + 4]);
            }
#pragma unroll
            for (int i = 0; i < 2; i++)
#pragma unroll
                for (int j = 0; j < 8; j++)
                    mma_tf32(acc[i][j], a[i], b[j]);
        }

        if (kt + 2 < KT) {
            __syncthreads();                 // all warps done with buf (kt&1)
            prefetch(kt + 2, kt & 1);
        }
    }

    // Epilogue (scalar stores; N may be odd)
#pragma unroll
    for (int i = 0; i < 2; i++) {
        int r0 = row0 + wm + 16 * i + g;
#pragma unroll
        for (int j = 0; j < 8; j++) {
            int c = col0 + wn + 8 * j + 2 * tg;
#pragma unroll
            for (int half = 0; half < 2; half++) {
                int r = r0 + half * 8;
#pragma unroll
                for (int e = 0; e < 2; e++) {
                    int cc = c + e;
                    if (cc < N) {
                        float v = acc[i][j][half * 2 + e];
                        if (bias)  v += bias[cc];
                        if (RELU)  v  = fmaxf(v, 0.f);
                        if (RESID) v += resid[(size_t)r * N + cc];
                        C[(size_t)r * N + cc] = v;
                    }
                }
            }
        }
    }
}

// ---------------------------------------------------------------------------
// Fused causal attention; qkv packed [m][1152] (q | k | v, head-interleaved)
// One block per (b, h, 64-query tile); 64 threads, thread = one query.
// ---------------------------------------------------------------------------
__global__ __launch_bounds__(64) void attn_kernel(const float* __restrict__ qkv,
                                                  float* __restrict__ out)
{
    __shared__ float Ks[64][64];
    __shared__ float Vs[64][64];

    int bh = blockIdx.x;
    int qt = blockIdx.y;
    int b = bh / NH, h = bh - b * NH;
    int t = qt * 64 + threadIdx.x;

    const float scale = rsqrtf((float)ND);
    size_t qrow = (size_t)(b * NT + t) * NQKV + h * NHD;

    float qr[NHD];
#pragma unroll
    for (int d = 0; d < NHD; d++) qr[d] = qkv[qrow + d] * scale;

    float o[NHD];
#pragma unroll
    for (int d = 0; d < NHD; d++) o[d] = 0.f;
    float mval = -1e30f, lsum = 0.f;

    for (int s0 = 0; s0 <= qt * 64; s0 += 64) {
        __syncthreads();
#pragma unroll 8
        for (int i = 0; i < 64; i++) {
            size_t kb = (size_t)(b * NT + s0 + i) * NQKV + h * NHD + threadIdx.x;
            Ks[i][threadIdx.x] = qkv[kb + ND];
            Vs[i][threadIdx.x] = qkv[kb + 2 * ND];
        }
        __syncthreads();
        int send = min(63, t - s0);
        for (int sr = 0; sr <= send; sr++) {
            float sc = 0.f;
#pragma unroll
            for (int d = 0; d < NHD; d++) sc += qr[d] * Ks[sr][d];
            float nm   = fmaxf(mval, sc);
            float corr = __expf(mval - nm);
            float p    = __expf(sc - nm);
            lsum = lsum * corr + p;
#pragma unroll
            for (int d = 0; d < NHD; d++) o[d] = o[d] * corr + p * Vs[sr][d];
            mval = nm;
        }
    }
    float inv = 1.f / lsum;
    size_t orow = (size_t)(b * NT + t) * ND + h * NHD;
#pragma unroll
    for (int d = 0; d < NHD; d++) out[orow + d] = o[d] * inv;
}

// ---------------------------------------------------------------------------
extern "C" void kernel_launch(void* const* d_in, const int* in_sizes, int n_in,
                              void* d_out, int out_size)
{
    const int*   idx   = (const int*)  d_in[0];
    const float* tok   = (const float*)d_in[1];
    const float* pos   = (const float*)d_in[2];
    const float* Wq    = (const float*)d_in[3];
    const float* Wk    = (const float*)d_in[4];
    const float* Wv    = (const float*)d_in[5];
    const float* Wproj = (const float*)d_in[6];
    const float* bproj = (const float*)d_in[7];
    const float* W1    = (const float*)d_in[8];
    const float* b1    = (const float*)d_in[9];
    const float* W2    = (const float*)d_in[10];
    const float* b2    = (const float*)d_in[11];
    const float* ln1g  = (const float*)d_in[12];
    const float* ln1b  = (const float*)d_in[13];
    const float* ln2g  = (const float*)d_in[14];
    const float* ln2b  = (const float*)d_in[15];
    const float* lnfg  = (const float*)d_in[16];
    const float* lnfb  = (const float*)d_in[17];
    const float* Whead = (const float*)d_in[18];
    const float* bhead = (const float*)d_in[19];
    float* out = (float*)d_out;

    float *px, *ph, *pqkv, *pa, *pm, *pw;
    cudaGetSymbolAddress((void**)&px,   g_x);
    cudaGetSymbolAddress((void**)&ph,   g_h);
    cudaGetSymbolAddress((void**)&pqkv, g_qkv);
    cudaGetSymbolAddress((void**)&pa,   g_att);
    cudaGetSymbolAddress((void**)&pm,   g_hid);
    cudaGetSymbolAddress((void**)&pw,   g_wT);

    static int attr_done = 0;
    if (!attr_done) {
        cudaFuncSetAttribute(tc_gemm<false, false>,
                             cudaFuncAttributeMaxDynamicSharedMemorySize, SM_BYTES);
        cudaFuncSetAttribute(tc_gemm<false, true>,
                             cudaFuncAttributeMaxDynamicSharedMemorySize, SM_BYTES);
        cudaFuncSetAttribute(tc_gemm<true, false>,
                             cudaFuncAttributeMaxDynamicSharedMemorySize, SM_BYTES);
        attr_done = 1;
    }

    // Weight transposes (tf32-rounded, K-major)
    qkvT_kernel<<<(NL * NQKV * ND) / 256, 256>>>(Wq, Wk, Wv, pw + OFF_QKV);
    transT_kernel<<<(NL * ND * ND)  / 256, 256>>>(Wproj, pw + OFF_PROJ, ND, ND);
    transT_kernel<<<(NL * ND4 * ND) / 256, 256>>>(W1, pw + OFF_W1, ND, ND4);
    transT_kernel<<<(NL * ND * ND4) / 256, 256>>>(W2, pw + OFF_W2, ND4, ND);
    transT_kernel<<<(NV * ND + 255) / 256, 256>>>(Whead, pw + OFF_HEAD, ND, NV);

    embed_kernel<<<(MT * ND) / 256, 256>>>(idx, tok, pos, px);

    const int MTILES = MT / 128;             // 128
    dim3 gQKV(NQKV / 128, MTILES);           // 9 x 128
    dim3 gD  (ND   / 128, MTILES);           // 3 x 128
    dim3 g4  (ND4  / 128, MTILES);           // 12 x 128
    dim3 gH  (1, MTILES);

    for (int l = 0; l < NL; l++) {
        ln_kernel<<<MT, 128>>>(px, ln1g + l * ND, ln1b + l * ND, ph);

        tc_gemm<false, false><<<gQKV, 256, SM_BYTES>>>(
            ph, pw + OFF_QKV + (size_t)l * NQKV * ND,
            nullptr, nullptr, pqkv, NQKV, ND);

        attn_kernel<<<dim3(NB * NH, NT / 64), 64>>>(pqkv, pa);

        tc_gemm<false, true><<<gD, 256, SM_BYTES>>>(
            pa, pw + OFF_PROJ + (size_t)l * ND * ND,
            bproj + l * ND, px, px, ND, ND);

        ln_kernel<<<MT, 128>>>(px, ln2g + l * ND, ln2b + l * ND, ph);

        tc_gemm<true, false><<<g4, 256, SM_BYTES>>>(
            ph, pw + OFF_W1 + (size_t)l * ND4 * ND,
            b1 + l * ND4, nullptr, pm, ND4, ND);

        tc_gemm<false, true><<<gD, 256, SM_BYTES>>>(
            pm, pw + OFF_W2 + (size_t)l * ND * ND4,
            b2 + l * ND, px, px, ND, ND4);
    }

    ln_kernel<<<MT, 128>>>(px, lnfg, lnfb, ph);
    tc_gemm<false, false><<<gH, 256, SM_BYTES>>>(
        ph, pw + OFF_HEAD, bhead, nullptr, out, NV, ND);
}

// round 4
// speedup vs baseline: 3.0341x; 1.2451x over previous
#include <cuda_runtime.h>
#include <cstdint>
#include <math.h>

// ---------------------------------------------------------------------------
// Problem constants
// ---------------------------------------------------------------------------
constexpr int NV  = 65;
constexpr int ND  = 384;
constexpr int NH  = 6;
constexpr int NHD = 64;
constexpr int NL  = 6;
constexpr int NT  = 256;
constexpr int NB  = 64;
constexpr int MT  = NB * NT;       // 16384
constexpr int ND4 = 4 * ND;        // 1536
constexpr int NQKV = 3 * ND;       // 1152

// ---------------------------------------------------------------------------
// Scratch (__device__ globals; allocation-free)
// ---------------------------------------------------------------------------
__device__ float g_x  [MT * ND];
__device__ float g_h  [MT * ND];
__device__ float g_qkv[MT * NQKV];
__device__ float g_att[MT * ND];
__device__ float g_hid[MT * ND4];

constexpr size_t OFF_QKV  = 0;
constexpr size_t OFF_PROJ = OFF_QKV  + (size_t)NL * NQKV * ND;
constexpr size_t OFF_W1   = OFF_PROJ + (size_t)NL * ND * ND;
constexpr size_t OFF_W2   = OFF_W1   + (size_t)NL * ND4 * ND;
constexpr size_t OFF_HEAD = OFF_W2   + (size_t)NL * ND * ND4;
constexpr size_t WT_TOTAL = OFF_HEAD + (size_t)NV * ND;
__device__ float g_wT[WT_TOTAL];

// ---------------------------------------------------------------------------
// Helpers
// ---------------------------------------------------------------------------
// K-permutation (within groups of 8): phys = P(logical); fragment pairs
// {k+tg, k+tg+4} land on adjacent phys slots {2tg, 2tg+1}.
__device__ __forceinline__ int Pf(int d) {
    return (d & ~7) | ((d & 3) << 1) | ((d >> 2) & 1);
}
__device__ __forceinline__ int Pinv(int d) {
    return (d & ~7) | ((d >> 1) & 3) | ((d & 1) << 2);
}

__device__ __forceinline__ uint32_t smem_u32(const void* p) {
    uint32_t a;
    asm("{ .reg .u64 t; cvta.to.shared.u64 t, %1; cvt.u32.u64 %0, t; }"
        : "=r"(a) : "l"(p));
    return a;
}
__device__ __forceinline__ float tf32r(float x) {
    uint32_t o;
    asm("cvt.rna.tf32.f32 %0, %1;" : "=r"(o) : "f"(x));
    return __uint_as_float(o);
}
__device__ __forceinline__ void cp16(uint32_t dst, const float* src, int srcsize) {
    asm volatile("cp.async.cg.shared.global [%0], [%1], 16, %2;"
                 :: "r"(dst), "l"(src), "r"(srcsize) : "memory");
}
__device__ __forceinline__ void cp_commit() {
    asm volatile("cp.async.commit_group;" ::: "memory");
}
__device__ __forceinline__ void mma_tf32(float* c, const uint32_t* a, const uint32_t* b) {
    asm volatile(
        "mma.sync.aligned.m16n8k8.row.col.f32.tf32.tf32.f32 "
        "{%0,%1,%2,%3}, {%4,%5,%6,%7}, {%8,%9}, {%0,%1,%2,%3};"
        : "+f"(c[0]), "+f"(c[1]), "+f"(c[2]), "+f"(c[3])
        : "r"(a[0]), "r"(a[1]), "r"(a[2]), "r"(a[3]), "r"(b[0]), "r"(b[1]));
}

// ---------------------------------------------------------------------------
// Embedding -> permuted-column layout (phys p holds logical Pinv(p))
// ---------------------------------------------------------------------------
__global__ void embed_kernel(const int* __restrict__ idx,
                             const float* __restrict__ tok,
                             const float* __restrict__ pos,
                             float* __restrict__ out)
{
    int gid = blockIdx.x * blockDim.x + threadIdx.x;
    int m = gid / ND, p = gid - m * ND;
    int d = Pinv(p);
    out[gid] = tok[(size_t)idx[m] * ND + d] + pos[(m % NT) * ND + d];
}

// ---------------------------------------------------------------------------
// LayerNorm (eps 1e-3); permuted layout in/out; output tf32-pre-rounded
// ---------------------------------------------------------------------------
__global__ __launch_bounds__(128) void ln_kernel(const float* __restrict__ x,
                                                 const float* __restrict__ g,
                                                 const float* __restrict__ bb,
                                                 float* __restrict__ out)
{
    int row = blockIdx.x, tid = threadIdx.x;
    const float* xr = x + (size_t)row * ND;
    float xv[3], s1 = 0.f, s2 = 0.f;
#pragma unroll
    for (int j = 0; j < 3; j++) {
        float v = xr[tid + j * 128];
        xv[j] = v; s1 += v; s2 += v * v;
    }
#pragma unroll
    for (int o = 16; o > 0; o >>= 1) {
        s1 += __shfl_down_sync(0xFFFFFFFFu, s1, o);
        s2 += __shfl_down_sync(0xFFFFFFFFu, s2, o);
    }
    __shared__ float sh1[4], sh2[4];
    int w = tid >> 5;
    if ((tid & 31) == 0) { sh1[w] = s1; sh2[w] = s2; }
    __syncthreads();
    s1 = sh1[0] + sh1[1] + sh1[2] + sh1[3];
    s2 = sh2[0] + sh2[1] + sh2[2] + sh2[3];
    float mean = s1 * (1.f / ND);
    float var  = s2 * (1.f / ND) - mean * mean;
    float rstd = rsqrtf(var + 1e-3f);
#pragma unroll
    for (int j = 0; j < 3; j++) {
        int c = tid + j * 128;
        int lc = Pinv(c);
        out[(size_t)row * ND + c] = tf32r((xv[j] - mean) * rstd * g[lc] + bb[lc]);
    }
}

// ---------------------------------------------------------------------------
// Weight transposes -> K-major [N,K], K (and optionally N) permuted, tf32
// ---------------------------------------------------------------------------
__global__ void qkvT_kernel(const float* __restrict__ Wq,
                            const float* __restrict__ Wk,
                            const float* __restrict__ Wv,
                            float* __restrict__ dst)
{
    int gid = blockIdx.x * blockDim.x + threadIdx.x;
    int k = gid % ND;
    int rest = gid / ND;
    int n = rest % NQKV;
    int l = rest / NQKV;
    int which = n / ND, nn = n % ND;
    int h = nn / NHD, hd = nn % NHD;
    const float* src = (which == 0) ? Wq : (which == 1) ? Wk : Wv;
    float v = src[(((size_t)l * NH + h) * ND + k) * NHD + hd];
    dst[((size_t)l * NQKV + Pf(n)) * ND + Pf(k)] = tf32r(v);
}

template <bool PERM_N>
__global__ void transT_kernel(const float* __restrict__ src,
                              float* __restrict__ dst, int Kd, int Nd)
{
    int gid = blockIdx.x * blockDim.x + threadIdx.x;
    int k = gid % Kd;
    int rest = gid / Kd;
    int n = rest % Nd;
    int l = rest / Nd;
    int np = PERM_N ? Pf(n) : n;
    dst[((size_t)l * Nd + np) * Kd + Pf(k)] =
        tf32r(src[((size_t)l * Kd + k) * Nd + n]);
}

// ---------------------------------------------------------------------------
// tf32 mma.sync GEMM: C[M,N] = A[M,K] * B^T  (B [N,K] K-major, both with
// permuted K; A pre-rounded to tf32). Tile 128x128x32; 8 warps 4Mx2N.
// Row stride 40 floats -> conflict-free 64-bit fragment loads.
// ---------------------------------------------------------------------------
constexpr int RS = 40;
constexpr int TILE_F = 128 * RS;             // 5120 floats
constexpr int SM_BYTES = 4 * TILE_F * 4;     // 81920

template <bool RELU, bool RESID, bool ROUND, bool PBIAS>
__global__ __launch_bounds__(256) void tc_gemm(
    const float* __restrict__ A, const float* __restrict__ B,
    const float* __restrict__ bias, const float* __restrict__ resid,
    float* __restrict__ C, int N, int K)
{
    extern __shared__ float smf[];
    __shared__ float sbias[128];
    const int tid = threadIdx.x;
    const int row0 = blockIdx.y * 128;
    const int col0 = blockIdx.x * 128;

    float* sA[2] = { smf, smf + TILE_F };
    float* sB[2] = { smf + 2 * TILE_F, smf + 3 * TILE_F };
    uint32_t sAu[2] = { smem_u32(sA[0]), smem_u32(sA[1]) };
    uint32_t sBu[2] = { smem_u32(sB[0]), smem_u32(sB[1]) };

    if (tid < 128) {
        int c = col0 + tid;
        float bv = 0.f;
        if (bias && c < N) bv = bias[PBIAS ? Pinv(c) : c];
        sbias[tid] = bv;
    }

    const int KT = K / 32;

    auto prefetch = [&](int kt, int bb) {
#pragma unroll
        for (int i = 0; i < 4; i++) {
            int slot = tid + i * 256;
            int r = slot >> 3, c4 = slot & 7;
            cp16(sAu[bb] + (uint32_t)(r * RS + c4 * 4) * 4,
                 A + (size_t)(row0 + r) * K + kt * 32 + c4 * 4, 16);
            int n = col0 + r;
            const float* src = B + (size_t)(n < N ? n : N - 1) * K + kt * 32 + c4 * 4;
            cp16(sBu[bb] + (uint32_t)(r * RS + c4 * 4) * 4, src, n < N ? 16 : 0);
        }
        cp_commit();
    };

    const int w = tid >> 5, lane = tid & 31;
    const int g = lane >> 2, tg = lane & 3;
    const int wm = (w & 3) * 32;
    const int wn = (w >> 2) * 64;

    float acc[2][8][4];
#pragma unroll
    for (int i = 0; i < 2; i++)
#pragma unroll
        for (int j = 0; j < 8; j++)
#pragma unroll
            for (int q = 0; q < 4; q++) acc[i][j][q] = 0.f;

    prefetch(0, 0);
    if (KT > 1) prefetch(1, 1);

    for (int kt = 0; kt < KT; kt++) {
        if (kt == KT - 1) asm volatile("cp.async.wait_group 0;" ::: "memory");
        else              asm volatile("cp.async.wait_group 1;" ::: "memory");
        __syncthreads();

        const float2* cA = (const float2*)sA[kt & 1];
        const float2* cB = (const float2*)sB[kt & 1];
#pragma unroll
        for (int kk = 0; kk < 4; kk++) {
            const int kb = kk * 4 + tg;
            uint32_t a[2][4];
#pragma unroll
            for (int i = 0; i < 2; i++) {
                int r = wm + 16 * i + g;
                float2 v0 = cA[r * (RS / 2) + kb];
                float2 v1 = cA[(r + 8) * (RS / 2) + kb];
                a[i][0] = __float_as_uint(v0.x);
                a[i][2] = __float_as_uint(v0.y);
                a[i][1] = __float_as_uint(v1.x);
                a[i][3] = __float_as_uint(v1.y);
            }
            uint32_t b[8][2];
#pragma unroll
            for (int j = 0; j < 8; j++) {
                float2 v = cB[(wn + 8 * j + g) * (RS / 2) + kb];
                b[j][0] = __float_as_uint(v.x);
                b[j][1] = __float_as_uint(v.y);
            }
#pragma unroll
            for (int i = 0; i < 2; i++)
#pragma unroll
                for (int j = 0; j < 8; j++)
                    mma_tf32(acc[i][j], a[i], b[j]);
        }

        if (kt + 2 < KT) {
            __syncthreads();
            prefetch(kt + 2, kt & 1);
        }
    }

    // Epilogue
    const bool vec = (N & 127) == 0;   // all but head gemm
#pragma unroll
    for (int i = 0; i < 2; i++) {
#pragma unroll
        for (int half = 0; half < 2; half++) {
            int r = row0 + wm + 16 * i + g + 8 * half;
#pragma unroll
            for (int j = 0; j < 8; j++) {
                int cl = wn + 8 * j + 2 * tg;
                int c = col0 + cl;
                float2 v = { acc[i][j][half * 2], acc[i][j][half * 2 + 1] };
                float2 bv = *(const float2*)&sbias[cl];
                v.x += bv.x; v.y += bv.y;
                if (RELU) { v.x = fmaxf(v.x, 0.f); v.y = fmaxf(v.y, 0.f); }
                if (ROUND) { v.x = tf32r(v.x); v.y = tf32r(v.y); }
                if (vec) {
                    if (RESID) {
                        float2 rv = *(const float2*)&resid[(size_t)r * N + c];
                        v.x += rv.x; v.y += rv.y;
                    }
                    *(float2*)&C[(size_t)r * N + c] = v;
                } else {
                    if (c < N)     C[(size_t)r * N + c]     = v.x;
                    if (c + 1 < N) C[(size_t)r * N + c + 1] = v.y;
                }
            }
        }
    }
}

// ---------------------------------------------------------------------------
// Fused causal attention; qkv packed [m][1152], permuted cols (dot products
// invariant). One block per (b, h, 64-query tile); output tf32-pre-rounded.
// ---------------------------------------------------------------------------
__global__ __launch_bounds__(64) void attn_kernel(const float* __restrict__ qkv,
                                                  float* __restrict__ out)
{
    __shared__ float Ks[64][64];
    __shared__ float Vs[64][64];

    int bh = blockIdx.x;
    int qt = blockIdx.y;
    int b = bh / NH, h = bh - b * NH;
    int t = qt * 64 + threadIdx.x;

    const float scale = rsqrtf((float)ND);
    size_t qrow = (size_t)(b * NT + t) * NQKV + h * NHD;

    float qr[NHD];
#pragma unroll
    for (int d = 0; d < NHD; d++) qr[d] = qkv[qrow + d] * scale;

    float o[NHD];
#pragma unroll
    for (int d = 0; d < NHD; d++) o[d] = 0.f;
    float mval = -1e30f, lsum = 0.f;

    for (int s0 = 0; s0 <= qt * 64; s0 += 64) {
        __syncthreads();
#pragma unroll 8
        for (int i = 0; i < 64; i++) {
            size_t kb = (size_t)(b * NT + s0 + i) * NQKV + h * NHD + threadIdx.x;
            Ks[i][threadIdx.x] = qkv[kb + ND];
            Vs[i][threadIdx.x] = qkv[kb + 2 * ND];
        }
        __syncthreads();
        int send = min(63, t - s0);
        for (int sr = 0; sr <= send; sr++) {
            float sc = 0.f;
#pragma unroll
            for (int d = 0; d < NHD; d++) sc += qr[d] * Ks[sr][d];
            float nm   = fmaxf(mval, sc);
            float corr = __expf(mval - nm);
            float p    = __expf(sc - nm);
            lsum = lsum * corr + p;
#pragma unroll
            for (int d = 0; d < NHD; d++) o[d] = o[d] * corr + p * Vs[sr][d];
            mval = nm;
        }
    }
    float inv = 1.f / lsum;
    size_t orow = (size_t)(b * NT + t) * ND + h * NHD;
#pragma unroll
    for (int d = 0; d < NHD; d++) out[orow + d] = tf32r(o[d] * inv);
}

// ---------------------------------------------------------------------------
extern "C" void kernel_launch(void* const* d_in, const int* in_sizes, int n_in,
                              void* d_out, int out_size)
{
    const int*   idx   = (const int*)  d_in[0];
    const float* tok   = (const float*)d_in[1];
    const float* pos   = (const float*)d_in[2];
    const float* Wq    = (const float*)d_in[3];
    const float* Wk    = (const float*)d_in[4];
    const float* Wv    = (const float*)d_in[5];
    const float* Wproj = (const float*)d_in[6];
    const float* bproj = (const float*)d_in[7];
    const float* W1    = (const float*)d_in[8];
    const float* b1    = (const float*)d_in[9];
    const float* W2    = (const float*)d_in[10];
    const float* b2    = (const float*)d_in[11];
    const float* ln1g  = (const float*)d_in[12];
    const float* ln1b  = (const float*)d_in[13];
    const float* ln2g  = (const float*)d_in[14];
    const float* ln2b  = (const float*)d_in[15];
    const float* lnfg  = (const float*)d_in[16];
    const float* lnfb  = (const float*)d_in[17];
    const float* Whead = (const float*)d_in[18];
    const float* bhead = (const float*)d_in[19];
    float* out = (float*)d_out;

    float *px, *ph, *pqkv, *pa, *pm, *pw;
    cudaGetSymbolAddress((void**)&px,   g_x);
    cudaGetSymbolAddress((void**)&ph,   g_h);
    cudaGetSymbolAddress((void**)&pqkv, g_qkv);
    cudaGetSymbolAddress((void**)&pa,   g_att);
    cudaGetSymbolAddress((void**)&pm,   g_hid);
    cudaGetSymbolAddress((void**)&pw,   g_wT);

    static int attr_done = 0;
    if (!attr_done) {
        cudaFuncSetAttribute(tc_gemm<false, false, false, true>,
                             cudaFuncAttributeMaxDynamicSharedMemorySize, SM_BYTES);
        cudaFuncSetAttribute(tc_gemm<false, true, false, true>,
                             cudaFuncAttributeMaxDynamicSharedMemorySize, SM_BYTES);
        cudaFuncSetAttribute(tc_gemm<true, false, true, true>,
                             cudaFuncAttributeMaxDynamicSharedMemorySize, SM_BYTES);
        cudaFuncSetAttribute(tc_gemm<false, false, false, false>,
                             cudaFuncAttributeMaxDynamicSharedMemorySize, SM_BYTES);
        attr_done = 1;
    }

    // Weight prep (K-major, K-permuted, tf32-rounded)
    qkvT_kernel<<<(NL * NQKV * ND) / 256, 256>>>(Wq, Wk, Wv, pw + OFF_QKV);
    transT_kernel<true><<<(NL * ND * ND)  / 256, 256>>>(Wproj, pw + OFF_PROJ, ND, ND);
    transT_kernel<true><<<(NL * ND4 * ND) / 256, 256>>>(W1, pw + OFF_W1, ND, ND4);
    transT_kernel<true><<<(NL * ND * ND4) / 256, 256>>>(W2, pw + OFF_W2, ND4, ND);
    transT_kernel<false><<<(NV * ND + 255) / 256, 256>>>(Whead, pw + OFF_HEAD, ND, NV);

    embed_kernel<<<(MT * ND) / 256, 256>>>(idx, tok, pos, px);

    const int MTILES = MT / 128;
    dim3 gQKV(NQKV / 128, MTILES);
    dim3 gD  (ND   / 128, MTILES);
    dim3 g4  (ND4  / 128, MTILES);
    dim3 gH  (1, MTILES);

    for (int l = 0; l < NL; l++) {
        ln_kernel<<<MT, 128>>>(px, ln1g + l * ND, ln1b + l * ND, ph);

        tc_gemm<false, false, false, true><<<gQKV, 256, SM_BYTES>>>(
            ph, pw + OFF_QKV + (size_t)l * NQKV * ND,
            nullptr, nullptr, pqkv, NQKV, ND);

        attn_kernel<<<dim3(NB * NH, NT / 64), 64>>>(pqkv, pa);

        tc_gemm<false, true, false, true><<<gD, 256, SM_BYTES>>>(
            pa, pw + OFF_PROJ + (size_t)l * ND * ND,
            bproj + l * ND, px, px, ND, ND);

        ln_kernel<<<MT, 128>>>(px, ln2g + l * ND, ln2b + l * ND, ph);

        tc_gemm<true, false, true, true><<<g4, 256, SM_BYTES>>>(
            ph, pw + OFF_W1 + (size_t)l * ND4 * ND,
            b1 + l * ND4, nullptr, pm, ND4, ND);

        tc_gemm<false, true, false, true><<<gD, 256, SM_BYTES>>>(
            pm, pw + OFF_W2 + (size_t)l * ND * ND4,
            b2 + l * ND, px, px, ND, ND4);
    }

    ln_kernel<<<MT, 128>>>(px, lnfg, lnfb, ph);
    tc_gemm<false, false, false, false><<<gH, 256, SM_BYTES>>>(
        ph, pw + OFF_HEAD, bhead, nullptr, out, NV, ND);
}

// round 5
// speedup vs baseline: 4.3261x; 1.4258x over previous
#include <cuda_runtime.h>
#include <cuda_fp16.h>
#include <cstdint>
#include <math.h>

// ---------------------------------------------------------------------------
// Problem constants
// ---------------------------------------------------------------------------
constexpr int NV  = 65;
constexpr int ND  = 384;
constexpr int NH  = 6;
constexpr int NHD = 64;
constexpr int NL  = 6;
constexpr int NT  = 256;
constexpr int NB  = 64;
constexpr int MT  = NB * NT;       // 16384
constexpr int ND4 = 4 * ND;        // 1536
constexpr int NQKV = 3 * ND;       // 1152

// ---------------------------------------------------------------------------
// Scratch (__device__ globals; allocation-free)
// ---------------------------------------------------------------------------
__device__ float  g_x   [MT * ND];      // fp32 residual stream
__device__ __half g_h16 [MT * ND];      // LN output (GEMM A)
__device__ __half g_qkv [MT * NQKV];
__device__ __half g_att [MT * ND];
__device__ __half g_hid [MT * ND4];

constexpr size_t OFF_QKV  = 0;
constexpr size_t OFF_PROJ = OFF_QKV  + (size_t)NL * NQKV * ND;
constexpr size_t OFF_W1   = OFF_PROJ + (size_t)NL * ND * ND;
constexpr size_t OFF_W2   = OFF_W1   + (size_t)NL * ND4 * ND;
constexpr size_t OFF_HEAD = OFF_W2   + (size_t)NL * ND * ND4;
constexpr size_t WT_TOTAL = OFF_HEAD + (size_t)NV * ND;
__device__ __half g_wT[WT_TOTAL];

// ---------------------------------------------------------------------------
// Helpers
// ---------------------------------------------------------------------------
__device__ __forceinline__ uint32_t smem_u32(const void* p) {
    uint32_t a;
    asm("{ .reg .u64 t; cvta.to.shared.u64 t, %1; cvt.u32.u64 %0, t; }"
        : "=r"(a) : "l"(p));
    return a;
}
__device__ __forceinline__ void cp16(uint32_t dst, const void* src, int srcsize) {
    asm volatile("cp.async.cg.shared.global [%0], [%1], 16, %2;"
                 :: "r"(dst), "l"(src), "r"(srcsize) : "memory");
}
__device__ __forceinline__ void cp_commit() {
    asm volatile("cp.async.commit_group;" ::: "memory");
}
__device__ __forceinline__ void ldm4(uint32_t* r, uint32_t a) {
    asm volatile("ldmatrix.sync.aligned.m8n8.x4.shared.b16 {%0,%1,%2,%3}, [%4];"
                 : "=r"(r[0]), "=r"(r[1]), "=r"(r[2]), "=r"(r[3]) : "r"(a));
}
__device__ __forceinline__ void mma_f16(float* c, const uint32_t* a,
                                        uint32_t b0, uint32_t b1) {
    asm volatile(
        "mma.sync.aligned.m16n8k16.row.col.f32.f16.f16.f32 "
        "{%0,%1,%2,%3}, {%4,%5,%6,%7}, {%8,%9}, {%0,%1,%2,%3};"
        : "+f"(c[0]), "+f"(c[1]), "+f"(c[2]), "+f"(c[3])
        : "r"(a[0]), "r"(a[1]), "r"(a[2]), "r"(a[3]), "r"(b0), "r"(b1));
}

// ---------------------------------------------------------------------------
// Embedding (fp32 residual stream)
// ---------------------------------------------------------------------------
__global__ void embed_kernel(const int* __restrict__ idx,
                             const float* __restrict__ tok,
                             const float* __restrict__ pos,
                             float* __restrict__ out)
{
    int gid = blockIdx.x * blockDim.x + threadIdx.x;
    int m = gid / ND, d = gid - m * ND;
    out[gid] = tok[(size_t)idx[m] * ND + d] + pos[(m % NT) * ND + d];
}

// ---------------------------------------------------------------------------
// LayerNorm (eps 1e-3), fp32 in -> fp16 out (feeds GEMM A)
// ---------------------------------------------------------------------------
__global__ __launch_bounds__(128) void ln_kernel(const float* __restrict__ x,
                                                 const float* __restrict__ g,
                                                 const float* __restrict__ bb,
                                                 __half* __restrict__ out)
{
    int row = blockIdx.x, tid = threadIdx.x;
    const float* xr = x + (size_t)row * ND;
    float xv[3], s1 = 0.f, s2 = 0.f;
#pragma unroll
    for (int j = 0; j < 3; j++) {
        float v = xr[tid + j * 128];
        xv[j] = v; s1 += v; s2 += v * v;
    }
#pragma unroll
    for (int o = 16; o > 0; o >>= 1) {
        s1 += __shfl_down_sync(0xFFFFFFFFu, s1, o);
        s2 += __shfl_down_sync(0xFFFFFFFFu, s2, o);
    }
    __shared__ float sh1[4], sh2[4];
    int w = tid >> 5;
    if ((tid & 31) == 0) { sh1[w] = s1; sh2[w] = s2; }
    __syncthreads();
    s1 = sh1[0] + sh1[1] + sh1[2] + sh1[3];
    s2 = sh2[0] + sh2[1] + sh2[2] + sh2[3];
    float mean = s1 * (1.f / ND);
    float var  = s2 * (1.f / ND) - mean * mean;
    float rstd = rsqrtf(var + 1e-3f);
#pragma unroll
    for (int j = 0; j < 3; j++) {
        int c = tid + j * 128;
        out[(size_t)row * ND + c] = __float2half((xv[j] - mean) * rstd * g[c] + bb[c]);
    }
}

// ---------------------------------------------------------------------------
// Weight prep -> K-major [N,K] fp16
// ---------------------------------------------------------------------------
__global__ void qkvT_kernel(const float* __restrict__ Wq,
                            const float* __restrict__ Wk,
                            const float* __restrict__ Wv,
                            __half* __restrict__ dst)
{
    int gid = blockIdx.x * blockDim.x + threadIdx.x;
    int k = gid % ND;
    int rest = gid / ND;
    int n = rest % NQKV;
    int l = rest / NQKV;
    int which = n / ND, nn = n % ND;
    int h = nn / NHD, hd = nn % NHD;
    const float* src = (which == 0) ? Wq : (which == 1) ? Wk : Wv;
    dst[gid] = __float2half(src[(((size_t)l * NH + h) * ND + k) * NHD + hd]);
}

__global__ void transT_kernel(const float* __restrict__ src,
                              __half* __restrict__ dst, int Kd, int Nd)
{
    int gid = blockIdx.x * blockDim.x + threadIdx.x;
    int k = gid % Kd;
    int rest = gid / Kd;
    int n = rest % Nd;
    int l = rest / Nd;
    dst[gid] = __float2half(src[((size_t)l * Kd + k) * Nd + n]);
}

// ---------------------------------------------------------------------------
// fp16 mma.sync GEMM: C[M,N] = A[M,K] * B^T (B [N,K] K-major fp16)
// Tile 128x128x32; 8 warps (4M x 2N); warp tile 32x64 of m16n8k16.
// ldmatrix fragment loads; 4-stage cp.async ring; rows padded to 80B.
// ---------------------------------------------------------------------------
constexpr int RSH = 40;                      // halves per padded row
constexpr int TILE_H = 128 * RSH;            // 5120 halves / buffer
constexpr int NSTAGE = 4;
constexpr int SM_BYTES = 2 * NSTAGE * TILE_H * 2;  // 81920

template <bool RELU, bool RESID, bool OUTH>
__global__ __launch_bounds__(256) void hgemm(
    const __half* __restrict__ A, const __half* __restrict__ B,
    const float* __restrict__ bias, const float* __restrict__ resid,
    void* __restrict__ Cv, int N, int K)
{
    extern __shared__ __half smh[];
    __shared__ float sbias[128];
    const int tid = threadIdx.x;
    const int row0 = blockIdx.y * 128;
    const int col0 = blockIdx.x * 128;

    uint32_t aAu[NSTAGE], aBu[NSTAGE];
#pragma unroll
    for (int s = 0; s < NSTAGE; s++) {
        aAu[s] = smem_u32(smh + s * TILE_H);
        aBu[s] = smem_u32(smh + (NSTAGE + s) * TILE_H);
    }

    if (tid < 128) {
        int c = col0 + tid;
        sbias[tid] = (bias && c < N) ? bias[c] : 0.f;
    }

    const int KT = K / 32;

    auto prefetch = [&](int kt, int s) {
#pragma unroll
        for (int i = 0; i < 2; i++) {
            int slot = tid + i * 256;          // 0..511
            int r = slot >> 2, c8 = slot & 3;  // row, 8-half chunk
            cp16(aAu[s] + (uint32_t)(r * 80 + c8 * 16),
                 A + (size_t)(row0 + r) * K + kt * 32 + c8 * 8, 16);
        }
#pragma unroll
        for (int i = 0; i < 2; i++) {
            int slot = tid + i * 256;
            int r = slot >> 2, c8 = slot & 3;
            int n = col0 + r;
            cp16(aBu[s] + (uint32_t)(r * 80 + c8 * 16),
                 B + (size_t)(n < N ? n : N - 1) * K + kt * 32 + c8 * 8,
                 n < N ? 16 : 0);
        }
        cp_commit();
    };

    const int w = tid >> 5, lane = tid & 31;
    const int wm = (w & 3) * 32;
    const int wn = (w >> 2) * 64;
    const int g = lane >> 2, tg = lane & 3;
    const int lr = lane & 15, lc = (lane >> 4) * 16;  // ldmatrix row / col bytes

    float acc[2][8][4];
#pragma unroll
    for (int i = 0; i < 2; i++)
#pragma unroll
        for (int j = 0; j < 8; j++)
#pragma unroll
            for (int q = 0; q < 4; q++) acc[i][j][q] = 0.f;

    prefetch(0, 0); prefetch(1, 1); prefetch(2, 2);

    for (int kt = 0; kt < KT; kt++) {
        int rem = KT - 1 - kt;
        if (rem >= 2)      asm volatile("cp.async.wait_group 2;" ::: "memory");
        else if (rem == 1) asm volatile("cp.async.wait_group 1;" ::: "memory");
        else               asm volatile("cp.async.wait_group 0;" ::: "memory");
        __syncthreads();

        if (kt + 3 < KT) prefetch(kt + 3, (kt + 3) & 3);

        uint32_t bA = aAu[kt & 3], bB = aBu[kt & 3];
#pragma unroll
        for (int ks = 0; ks < 2; ks++) {
            uint32_t a[2][4];
#pragma unroll
            for (int i = 0; i < 2; i++)
                ldm4(a[i], bA + (uint32_t)((wm + 16 * i + lr) * 80 + ks * 32 + lc));
            uint32_t b[4][4];
#pragma unroll
            for (int p = 0; p < 4; p++)
                ldm4(b[p], bB + (uint32_t)((wn + 16 * p + lr) * 80 + ks * 32 + lc));
#pragma unroll
            for (int i = 0; i < 2; i++)
#pragma unroll
                for (int p = 0; p < 4; p++) {
                    mma_f16(acc[i][2 * p],     a[i], b[p][0], b[p][2]);
                    mma_f16(acc[i][2 * p + 1], a[i], b[p][1], b[p][3]);
                }
        }
    }

    // Epilogue
    const bool vec = (N & 127) == 0;
    float*  Cf = (float*)Cv;
    __half* Ch = (__half*)Cv;
#pragma unroll
    for (int i = 0; i < 2; i++) {
#pragma unroll
        for (int half_ = 0; half_ < 2; half_++) {
            int r = row0 + wm + 16 * i + g + 8 * half_;
#pragma unroll
            for (int j = 0; j < 8; j++) {
                int cl = wn + 8 * j + 2 * tg;
                int c = col0 + cl;
                float2 v = { acc[i][j][half_ * 2], acc[i][j][half_ * 2 + 1] };
                v.x += sbias[cl]; v.y += sbias[cl + 1];
                if (RELU) { v.x = fmaxf(v.x, 0.f); v.y = fmaxf(v.y, 0.f); }
                if (OUTH) {
                    *(__half2*)&Ch[(size_t)r * N + c] = __floats2half2_rn(v.x, v.y);
                } else if (vec) {
                    if (RESID) {
                        float2 rv = *(const float2*)&resid[(size_t)r * N + c];
                        v.x += rv.x; v.y += rv.y;
                    }
                    *(float2*)&Cf[(size_t)r * N + c] = v;
                } else {
                    if (c < N)     Cf[(size_t)r * N + c]     = v.x;
                    if (c + 1 < N) Cf[(size_t)r * N + c + 1] = v.y;
                }
            }
        }
    }
}

// ---------------------------------------------------------------------------
// Fused causal attention; qkv fp16 [m][1152] (q|k|v, head-major).
// Block = (b, h, 64-query tile); fp32 math; fp16 output.
// ---------------------------------------------------------------------------
__global__ __launch_bounds__(64) void attn_kernel(const __half* __restrict__ qkv,
                                                  __half* __restrict__ out)
{
    __shared__ float Ks[64][64];
    __shared__ float Vs[64][64];

    int bh = blockIdx.x;
    int qt = blockIdx.y;
    int b = bh / NH, h = bh - b * NH;
    int t = qt * 64 + threadIdx.x;

    const float scale = rsqrtf((float)ND);
    size_t qrow = (size_t)(b * NT + t) * NQKV + h * NHD;

    float qr[NHD];
#pragma unroll
    for (int d = 0; d < NHD; d++) qr[d] = __half2float(qkv[qrow + d]) * scale;

    float o[NHD];
#pragma unroll
    for (int d = 0; d < NHD; d++) o[d] = 0.f;
    float mval = -1e30f, lsum = 0.f;

    for (int s0 = 0; s0 <= qt * 64; s0 += 64) {
        __syncthreads();
#pragma unroll 8
        for (int i = 0; i < 64; i++) {
            size_t kb = (size_t)(b * NT + s0 + i) * NQKV + h * NHD + threadIdx.x;
            Ks[i][threadIdx.x] = __half2float(qkv[kb + ND]);
            Vs[i][threadIdx.x] = __half2float(qkv[kb + 2 * ND]);
        }
        __syncthreads();
        int send = min(63, t - s0);
        for (int sr = 0; sr <= send; sr++) {
            float sc = 0.f;
#pragma unroll
            for (int d = 0; d < NHD; d++) sc += qr[d] * Ks[sr][d];
            float nm   = fmaxf(mval, sc);
            float corr = __expf(mval - nm);
            float p    = __expf(sc - nm);
            lsum = lsum * corr + p;
#pragma unroll
            for (int d = 0; d < NHD; d++) o[d] = o[d] * corr + p * Vs[sr][d];
            mval = nm;
        }
    }
    float inv = 1.f / lsum;
    size_t orow = (size_t)(b * NT + t) * ND + h * NHD;
#pragma unroll
    for (int d = 0; d < NHD; d++) out[orow + d] = __float2half(o[d] * inv);
}

// ---------------------------------------------------------------------------
extern "C" void kernel_launch(void* const* d_in, const int* in_sizes, int n_in,
                              void* d_out, int out_size)
{
    const int*   idx   = (const int*)  d_in[0];
    const float* tok   = (const float*)d_in[1];
    const float* pos   = (const float*)d_in[2];
    const float* Wq    = (const float*)d_in[3];
    const float* Wk    = (const float*)d_in[4];
    const float* Wv    = (const float*)d_in[5];
    const float* Wproj = (const float*)d_in[6];
    const float* bproj = (const float*)d_in[7];
    const float* W1    = (const float*)d_in[8];
    const float* b1    = (const float*)d_in[9];
    const float* W2    = (const float*)d_in[10];
    const float* b2    = (const float*)d_in[11];
    const float* ln1g  = (const float*)d_in[12];
    const float* ln1b  = (const float*)d_in[13];
    const float* ln2g  = (const float*)d_in[14];
    const float* ln2b  = (const float*)d_in[15];
    const float* lnfg  = (const float*)d_in[16];
    const float* lnfb  = (const float*)d_in[17];
    const float* Whead = (const float*)d_in[18];
    const float* bhead = (const float*)d_in[19];
    float* out = (float*)d_out;

    float  *px;
    __half *ph, *pqkv, *pa, *pm, *pw;
    cudaGetSymbolAddress((void**)&px,   g_x);
    cudaGetSymbolAddress((void**)&ph,   g_h16);
    cudaGetSymbolAddress((void**)&pqkv, g_qkv);
    cudaGetSymbolAddress((void**)&pa,   g_att);
    cudaGetSymbolAddress((void**)&pm,   g_hid);
    cudaGetSymbolAddress((void**)&pw,   g_wT);

    static int attr_done = 0;
    if (!attr_done) {
        cudaFuncSetAttribute(hgemm<false, false, true>,
                             cudaFuncAttributeMaxDynamicSharedMemorySize, SM_BYTES);
        cudaFuncSetAttribute(hgemm<false, true, false>,
                             cudaFuncAttributeMaxDynamicSharedMemorySize, SM_BYTES);
        cudaFuncSetAttribute(hgemm<true, false, true>,
                             cudaFuncAttributeMaxDynamicSharedMemorySize, SM_BYTES);
        cudaFuncSetAttribute(hgemm<false, false, false>,
                             cudaFuncAttributeMaxDynamicSharedMemorySize, SM_BYTES);
        attr_done = 1;
    }

    // Weight prep (K-major fp16)
    qkvT_kernel<<<(NL * NQKV * ND) / 256, 256>>>(Wq, Wk, Wv, pw + OFF_QKV);
    transT_kernel<<<(NL * ND * ND)  / 256, 256>>>(Wproj, pw + OFF_PROJ, ND, ND);
    transT_kernel<<<(NL * ND4 * ND) / 256, 256>>>(W1, pw + OFF_W1, ND, ND4);
    transT_kernel<<<(NL * ND * ND4) / 256, 256>>>(W2, pw + OFF_W2, ND4, ND);
    transT_kernel<<<(NV * ND + 255) / 256, 256>>>(Whead, pw + OFF_HEAD, ND, NV);

    embed_kernel<<<(MT * ND) / 256, 256>>>(idx, tok, pos, px);

    const int MTILES = MT / 128;
    dim3 gQKV(NQKV / 128, MTILES);
    dim3 gD  (ND   / 128, MTILES);
    dim3 g4  (ND4  / 128, MTILES);
    dim3 gH  (1, MTILES);

    for (int l = 0; l < NL; l++) {
        ln_kernel<<<MT, 128>>>(px, ln1g + l * ND, ln1b + l * ND, ph);

        hgemm<false, false, true><<<gQKV, 256, SM_BYTES>>>(
            ph, pw + OFF_QKV + (size_t)l * NQKV * ND,
            nullptr, nullptr, pqkv, NQKV, ND);

        attn_kernel<<<dim3(NB * NH, NT / 64), 64>>>(pqkv, pa);

        hgemm<false, true, false><<<gD, 256, SM_BYTES>>>(
            pa, pw + OFF_PROJ + (size_t)l * ND * ND,
            bproj + l * ND, px, px, ND, ND);

        ln_kernel<<<MT, 128>>>(px, ln2g + l * ND, ln2b + l * ND, ph);

        hgemm<true, false, true><<<g4, 256, SM_BYTES>>>(
            ph, pw + OFF_W1 + (size_t)l * ND4 * ND,
            b1 + l * ND4, nullptr, pm, ND4, ND);

        hgemm<false, true, false><<<gD, 256, SM_BYTES>>>(
            pm, pw + OFF_W2 + (size_t)l * ND * ND4,
            b2 + l * ND, px, px, ND, ND4);
    }

    ln_kernel<<<MT, 128>>>(px, lnfg, lnfb, ph);
    hgemm<false, false, false><<<gH, 256, SM_BYTES>>>(
        ph, pw + OFF_HEAD, bhead, nullptr, out, NV, ND);
}

// round 6
// speedup vs baseline: 4.3891x; 1.0146x over previous
#include <cuda_runtime.h>
#include <cuda_fp16.h>
#include <cstdint>
#include <math.h>

// ---------------------------------------------------------------------------
// Problem constants
// ---------------------------------------------------------------------------
constexpr int NV  = 65;
constexpr int ND  = 384;
constexpr int NH  = 6;
constexpr int NHD = 64;
constexpr int NL  = 6;
constexpr int NT  = 256;
constexpr int NB  = 64;
constexpr int MT  = NB * NT;       // 16384
constexpr int ND4 = 4 * ND;        // 1536
constexpr int NQKV = 3 * ND;       // 1152

// ---------------------------------------------------------------------------
// Scratch (__device__ globals; allocation-free)
// ---------------------------------------------------------------------------
__device__ float  g_x   [MT * ND];      // fp32 residual stream
__device__ __half g_h16 [MT * ND];      // LN output (GEMM A)
__device__ __half g_qkv [MT * NQKV];
__device__ __half g_att [MT * ND];
__device__ __half g_hid [MT * ND4];

constexpr size_t OFF_QKV  = 0;
constexpr size_t OFF_PROJ = OFF_QKV  + (size_t)NL * NQKV * ND;
constexpr size_t OFF_W1   = OFF_PROJ + (size_t)NL * ND * ND;
constexpr size_t OFF_W2   = OFF_W1   + (size_t)NL * ND4 * ND;
constexpr size_t OFF_HEAD = OFF_W2   + (size_t)NL * ND * ND4;
constexpr size_t WT_TOTAL = OFF_HEAD + (size_t)NV * ND;
__device__ __half g_wT[WT_TOTAL];

// ---------------------------------------------------------------------------
// Helpers
// ---------------------------------------------------------------------------
__device__ __forceinline__ uint32_t smem_u32(const void* p) {
    uint32_t a;
    asm("{ .reg .u64 t; cvta.to.shared.u64 t, %1; cvt.u32.u64 %0, t; }"
        : "=r"(a) : "l"(p));
    return a;
}
__device__ __forceinline__ void cp16(uint32_t dst, const void* src, int srcsize) {
    asm volatile("cp.async.cg.shared.global [%0], [%1], 16, %2;"
                 :: "r"(dst), "l"(src), "r"(srcsize) : "memory");
}
__device__ __forceinline__ void cp_commit() {
    asm volatile("cp.async.commit_group;" ::: "memory");
}
__device__ __forceinline__ void ldm4(uint32_t* r, uint32_t a) {
    asm volatile("ldmatrix.sync.aligned.m8n8.x4.shared.b16 {%0,%1,%2,%3}, [%4];"
                 : "=r"(r[0]), "=r"(r[1]), "=r"(r[2]), "=r"(r[3]) : "r"(a));
}
__device__ __forceinline__ void mma_f16(float* c, const uint32_t* a,
                                        uint32_t b0, uint32_t b1) {
    asm volatile(
        "mma.sync.aligned.m16n8k16.row.col.f32.f16.f16.f32 "
        "{%0,%1,%2,%3}, {%4,%5,%6,%7}, {%8,%9}, {%0,%1,%2,%3};"
        : "+f"(c[0]), "+f"(c[1]), "+f"(c[2]), "+f"(c[3])
        : "r"(a[0]), "r"(a[1]), "r"(a[2]), "r"(a[3]), "r"(b0), "r"(b1));
}

// ---------------------------------------------------------------------------
// Embedding (fp32 residual stream)
// ---------------------------------------------------------------------------
__global__ void embed_kernel(const int* __restrict__ idx,
                             const float* __restrict__ tok,
                             const float* __restrict__ pos,
                             float* __restrict__ out)
{
    int gid = blockIdx.x * blockDim.x + threadIdx.x;
    int m = gid / ND, d = gid - m * ND;
    out[gid] = tok[(size_t)idx[m] * ND + d] + pos[(m % NT) * ND + d];
}

// ---------------------------------------------------------------------------
// LayerNorm (eps 1e-3), warp-per-row, fp32 in -> fp16 out
// 256 threads = 8 warps = 8 rows per block; lane handles 12 cols (3 float4).
// ---------------------------------------------------------------------------
__global__ __launch_bounds__(256) void ln_kernel(const float* __restrict__ x,
                                                 const float* __restrict__ g,
                                                 const float* __restrict__ bb,
                                                 __half* __restrict__ out)
{
    int w = threadIdx.x >> 5, lane = threadIdx.x & 31;
    int row = blockIdx.x * 8 + w;
    const float* xr = x + (size_t)row * ND;

    float4 xv[3];
    float s1 = 0.f, s2 = 0.f;
#pragma unroll
    for (int j = 0; j < 3; j++) {
        float4 v = *(const float4*)(xr + lane * 4 + j * 128);
        xv[j] = v;
        s1 += v.x + v.y + v.z + v.w;
        s2 += v.x * v.x + v.y * v.y + v.z * v.z + v.w * v.w;
    }
#pragma unroll
    for (int o = 16; o > 0; o >>= 1) {
        s1 += __shfl_xor_sync(0xFFFFFFFFu, s1, o);
        s2 += __shfl_xor_sync(0xFFFFFFFFu, s2, o);
    }
    float mean = s1 * (1.f / ND);
    float var  = s2 * (1.f / ND) - mean * mean;
    float rstd = rsqrtf(var + 1e-3f);
#pragma unroll
    for (int j = 0; j < 3; j++) {
        int c = lane * 4 + j * 128;
        float4 gv = *(const float4*)(g + c);
        float4 bv = *(const float4*)(bb + c);
        __half2 h0 = __floats2half2_rn((xv[j].x - mean) * rstd * gv.x + bv.x,
                                       (xv[j].y - mean) * rstd * gv.y + bv.y);
        __half2 h1 = __floats2half2_rn((xv[j].z - mean) * rstd * gv.z + bv.z,
                                       (xv[j].w - mean) * rstd * gv.w + bv.w);
        *(__half2*)(out + (size_t)row * ND + c)     = h0;
        *(__half2*)(out + (size_t)row * ND + c + 2) = h1;
    }
}

// ---------------------------------------------------------------------------
// Tiled transpose: src [R,C] fp32 (+batch offsets) -> dst [C,R] fp16.
// Batch z: offs = (z/div)*sA + (z%div)*sB (src), same pattern for dst.
// ---------------------------------------------------------------------------
__global__ void transpose_kernel(const float* __restrict__ src,
                                 __half* __restrict__ dst,
                                 int R, int C, int div,
                                 size_t ssA, size_t ssB,
                                 size_t dsA, size_t dsB)
{
    __shared__ float tile[32][33];
    int z = blockIdx.z;
    const float* s = src + (z / div) * ssA + (z % div) * ssB;
    __half* d = dst + (z / div) * dsA + (z % div) * dsB;
    int c0 = blockIdx.x * 32, r0 = blockIdx.y * 32;
#pragma unroll
    for (int j = 0; j < 4; j++) {
        int r = r0 + threadIdx.y + j * 8, c = c0 + threadIdx.x;
        if (r < R && c < C)
            tile[threadIdx.y + j * 8][threadIdx.x] = s[(size_t)r * C + c];
    }
    __syncthreads();
#pragma unroll
    for (int j = 0; j < 4; j++) {
        int c = c0 + threadIdx.y + j * 8, r = r0 + threadIdx.x;
        if (c < C && r < R)
            d[(size_t)c * R + r] = __float2half(tile[threadIdx.x][threadIdx.y + j * 8]);
    }
}

// ---------------------------------------------------------------------------
// fp16 mma.sync GEMM: C[M,N] = A[M,K] * B^T (B [N,K] K-major fp16)
// Tile 128x128x32; 4 warps (2M x 2N); warp tile 64x64 of m16n8k16.
// 16 ldmatrix.x4 : 64 mma per k-tile per warp; 4-stage cp.async ring.
// ---------------------------------------------------------------------------
constexpr int RSH = 40;                      // halves per padded row (80 B)
constexpr int TILE_H = 128 * RSH;            // 5120 halves / buffer
constexpr int NSTAGE = 4;
constexpr int SM_BYTES = 2 * NSTAGE * TILE_H * 2;  // 81920

template <bool RELU, bool RESID, bool OUTH>
__global__ __launch_bounds__(128) void hgemm(
    const __half* __restrict__ A, const __half* __restrict__ B,
    const float* __restrict__ bias, const float* __restrict__ resid,
    void* __restrict__ Cv, int N, int K)
{
    extern __shared__ __half smh[];
    __shared__ float sbias[128];
    const int tid = threadIdx.x;
    const int row0 = blockIdx.y * 128;
    const int col0 = blockIdx.x * 128;

    uint32_t aAu[NSTAGE], aBu[NSTAGE];
#pragma unroll
    for (int s = 0; s < NSTAGE; s++) {
        aAu[s] = smem_u32(smh + s * TILE_H);
        aBu[s] = smem_u32(smh + (NSTAGE + s) * TILE_H);
    }

    {
        int c = col0 + tid;
        sbias[tid] = (bias && c < N) ? bias[c] : 0.f;
    }

    const int KT = K / 32;

    auto prefetch = [&](int kt, int s) {
#pragma unroll
        for (int i = 0; i < 4; i++) {
            int slot = tid + i * 128;          // 0..511
            int r = slot >> 2, c8 = slot & 3;
            cp16(aAu[s] + (uint32_t)(r * 80 + c8 * 16),
                 A + (size_t)(row0 + r) * K + kt * 32 + c8 * 8, 16);
        }
#pragma unroll
        for (int i = 0; i < 4; i++) {
            int slot = tid + i * 128;
            int r = slot >> 2, c8 = slot & 3;
            int n = col0 + r;
            cp16(aBu[s] + (uint32_t)(r * 80 + c8 * 16),
                 B + (size_t)(n < N ? n : N - 1) * K + kt * 32 + c8 * 8,
                 n < N ? 16 : 0);
        }
        cp_commit();
    };

    const int w = tid >> 5, lane = tid & 31;
    const int wm = (w & 1) * 64;
    const int wn = (w >> 1) * 64;
    const int g = lane >> 2, tg = lane & 3;
    const int lr = lane & 15, lc = (lane >> 4) * 16;

    float acc[4][8][4];
#pragma unroll
    for (int i = 0; i < 4; i++)
#pragma unroll
        for (int j = 0; j < 8; j++)
#pragma unroll
            for (int q = 0; q < 4; q++) acc[i][j][q] = 0.f;

    prefetch(0, 0); prefetch(1, 1); prefetch(2, 2);

    for (int kt = 0; kt < KT; kt++) {
        int rem = KT - 1 - kt;
        if (rem >= 2)      asm volatile("cp.async.wait_group 2;" ::: "memory");
        else if (rem == 1) asm volatile("cp.async.wait_group 1;" ::: "memory");
        else               asm volatile("cp.async.wait_group 0;" ::: "memory");
        __syncthreads();

        if (kt + 3 < KT) prefetch(kt + 3, (kt + 3) & 3);

        uint32_t bA = aAu[kt & 3], bB = aBu[kt & 3];
#pragma unroll
        for (int ks = 0; ks < 2; ks++) {
            uint32_t a[4][4];
#pragma unroll
            for (int i = 0; i < 4; i++)
                ldm4(a[i], bA + (uint32_t)((wm + 16 * i + lr) * 80 + ks * 32 + lc));
            uint32_t b[4][4];
#pragma unroll
            for (int p = 0; p < 4; p++)
                ldm4(b[p], bB + (uint32_t)((wn + 16 * p + lr) * 80 + ks * 32 + lc));
#pragma unroll
            for (int i = 0; i < 4; i++)
#pragma unroll
                for (int p = 0; p < 4; p++) {
                    mma_f16(acc[i][2 * p],     a[i], b[p][0], b[p][2]);
                    mma_f16(acc[i][2 * p + 1], a[i], b[p][1], b[p][3]);
                }
        }
    }

    // Epilogue
    const bool vec = (N & 127) == 0;
    float*  Cf = (float*)Cv;
    __half* Ch = (__half*)Cv;
#pragma unroll
    for (int i = 0; i < 4; i++) {
#pragma unroll
        for (int half_ = 0; half_ < 2; half_++) {
            int r = row0 + wm + 16 * i + g + 8 * half_;
#pragma unroll
            for (int j = 0; j < 8; j++) {
                int cl = wn + 8 * j + 2 * tg;
                int c = col0 + cl;
                float2 v = { acc[i][j][half_ * 2], acc[i][j][half_ * 2 + 1] };
                v.x += sbias[cl]; v.y += sbias[cl + 1];
                if (RELU) { v.x = fmaxf(v.x, 0.f); v.y = fmaxf(v.y, 0.f); }
                if (OUTH) {
                    *(__half2*)&Ch[(size_t)r * N + c] = __floats2half2_rn(v.x, v.y);
                } else if (vec) {
                    if (RESID) {
                        float2 rv = *(const float2*)&resid[(size_t)r * N + c];
                        v.x += rv.x; v.y += rv.y;
                    }
                    *(float2*)&Cf[(size_t)r * N + c] = v;
                } else {
                    if (c < N)     Cf[(size_t)r * N + c]     = v.x;
                    if (c + 1 < N) Cf[(size_t)r * N + c + 1] = v.y;
                }
            }
        }
    }
}

// ---------------------------------------------------------------------------
// Fused causal attention; qkv fp16 [m][1152] (q|k|v, head-major).
// Block = (b, h, 64-query tile); fp32 math; fp16 output.
// ---------------------------------------------------------------------------
__global__ __launch_bounds__(64) void attn_kernel(const __half* __restrict__ qkv,
                                                  __half* __restrict__ out)
{
    __shared__ float Ks[64][64];
    __shared__ float Vs[64][64];

    int bh = blockIdx.x;
    int qt = blockIdx.y;
    int b = bh / NH, h = bh - b * NH;
    int t = qt * 64 + threadIdx.x;

    const float scale = rsqrtf((float)ND);
    size_t qrow = (size_t)(b * NT + t) * NQKV + h * NHD;

    float qr[NHD];
#pragma unroll
    for (int d = 0; d < NHD; d++) qr[d] = __half2float(qkv[qrow + d]) * scale;

    float o[NHD];
#pragma unroll
    for (int d = 0; d < NHD; d++) o[d] = 0.f;
    float mval = -1e30f, lsum = 0.f;

    for (int s0 = 0; s0 <= qt * 64; s0 += 64) {
        __syncthreads();
#pragma unroll 8
        for (int i = 0; i < 64; i++) {
            size_t kb = (size_t)(b * NT + s0 + i) * NQKV + h * NHD + threadIdx.x;
            Ks[i][threadIdx.x] = __half2float(qkv[kb + ND]);
            Vs[i][threadIdx.x] = __half2float(qkv[kb + 2 * ND]);
        }
        __syncthreads();
        int send = min(63, t - s0);
        for (int sr = 0; sr <= send; sr++) {
            float sc = 0.f;
#pragma unroll
            for (int d = 0; d < NHD; d++) sc += qr[d] * Ks[sr][d];
            float nm   = fmaxf(mval, sc);
            float corr = __expf(mval - nm);
            float p    = __expf(sc - nm);
            lsum = lsum * corr + p;
#pragma unroll
            for (int d = 0; d < NHD; d++) o[d] = o[d] * corr + p * Vs[sr][d];
            mval = nm;
        }
    }
    float inv = 1.f / lsum;
    size_t orow = (size_t)(b * NT + t) * ND + h * NHD;
#pragma unroll
    for (int d = 0; d < NHD; d++) out[orow + d] = __float2half(o[d] * inv);
}

// ---------------------------------------------------------------------------
extern "C" void kernel_launch(void* const* d_in, const int* in_sizes, int n_in,
                              void* d_out, int out_size)
{
    const int*   idx   = (const int*)  d_in[0];
    const float* tok   = (const float*)d_in[1];
    const float* pos   = (const float*)d_in[2];
    const float* Wq    = (const float*)d_in[3];
    const float* Wk    = (const float*)d_in[4];
    const float* Wv    = (const float*)d_in[5];
    const float* Wproj = (const float*)d_in[6];
    const float* bproj = (const float*)d_in[7];
    const float* W1    = (const float*)d_in[8];
    const float* b1    = (const float*)d_in[9];
    const float* W2    = (const float*)d_in[10];
    const float* b2    = (const float*)d_in[11];
    const float* ln1g  = (const float*)d_in[12];
    const float* ln1b  = (const float*)d_in[13];
    const float* ln2g  = (const float*)d_in[14];
    const float* ln2b  = (const float*)d_in[15];
    const float* lnfg  = (const float*)d_in[16];
    const float* lnfb  = (const float*)d_in[17];
    const float* Whead = (const float*)d_in[18];
    const float* bhead = (const float*)d_in[19];
    float* out = (float*)d_out;

    float  *px;
    __half *ph, *pqkv, *pa, *pm, *pw;
    cudaGetSymbolAddress((void**)&px,   g_x);
    cudaGetSymbolAddress((void**)&ph,   g_h16);
    cudaGetSymbolAddress((void**)&pqkv, g_qkv);
    cudaGetSymbolAddress((void**)&pa,   g_att);
    cudaGetSymbolAddress((void**)&pm,   g_hid);
    cudaGetSymbolAddress((void**)&pw,   g_wT);

    static int attr_done = 0;
    if (!attr_done) {
        cudaFuncSetAttribute(hgemm<false, false, true>,
                             cudaFuncAttributeMaxDynamicSharedMemorySize, SM_BYTES);
        cudaFuncSetAttribute(hgemm<false, true, false>,
                             cudaFuncAttributeMaxDynamicSharedMemorySize, SM_BYTES);
        cudaFuncSetAttribute(hgemm<true, false, true>,
                             cudaFuncAttributeMaxDynamicSharedMemorySize, SM_BYTES);
        cudaFuncSetAttribute(hgemm<false, false, false>,
                             cudaFuncAttributeMaxDynamicSharedMemorySize, SM_BYTES);
        attr_done = 1;
    }

    // Weight prep: tiled transpose -> K-major [N,K] fp16
    {
        dim3 blk(32, 8);
        // Q/K/V: per (l,h) transpose [D,HD] -> dst block at (l*1152 + which*384 + h*64)*ND
        dim3 gqv(NHD / 32, ND / 32, NL * NH);
        size_t ssA = (size_t)NH * ND * NHD, ssB = (size_t)ND * NHD;
        size_t dsA = (size_t)NQKV * ND,     dsB = (size_t)NHD * ND;
        transpose_kernel<<<gqv, blk>>>(Wq, pw + OFF_QKV,             ND, NHD, NH, ssA, ssB, dsA, dsB);
        transpose_kernel<<<gqv, blk>>>(Wk, pw + OFF_QKV + (size_t)ND * ND,     ND, NHD, NH, ssA, ssB, dsA, dsB);
        transpose_kernel<<<gqv, blk>>>(Wv, pw + OFF_QKV + (size_t)2 * ND * ND, ND, NHD, NH, ssA, ssB, dsA, dsB);
        // proj [D,D]
        transpose_kernel<<<dim3(ND / 32, ND / 32, NL), blk>>>(
            Wproj, pw + OFF_PROJ, ND, ND, 1, (size_t)ND * ND, 0, (size_t)ND * ND, 0);
        // W1 [D,4D]
        transpose_kernel<<<dim3(ND4 / 32, ND / 32, NL), blk>>>(
            W1, pw + OFF_W1, ND, ND4, 1, (size_t)ND * ND4, 0, (size_t)ND * ND4, 0);
        // W2 [4D,D]
        transpose_kernel<<<dim3(ND / 32, ND4 / 32, NL), blk>>>(
            W2, pw + OFF_W2, ND4, ND, 1, (size_t)ND * ND4, 0, (size_t)ND * ND4, 0);
        // head [D,V]
        transpose_kernel<<<dim3((NV + 31) / 32, ND / 32, 1), blk>>>(
            Whead, pw + OFF_HEAD, ND, NV, 1, 0, 0, 0, 0);
    }

    embed_kernel<<<(MT * ND) / 256, 256>>>(idx, tok, pos, px);

    const int MTILES = MT / 128;
    dim3 gQKV(NQKV / 128, MTILES);
    dim3 gD  (ND   / 128, MTILES);
    dim3 g4  (ND4  / 128, MTILES);
    dim3 gH  (1, MTILES);

    for (int l = 0; l < NL; l++) {
        ln_kernel<<<MT / 8, 256>>>(px, ln1g + l * ND, ln1b + l * ND, ph);

        hgemm<false, false, true><<<gQKV, 128, SM_BYTES>>>(
            ph, pw + OFF_QKV + (size_t)l * NQKV * ND,
            nullptr, nullptr, pqkv, NQKV, ND);

        attn_kernel<<<dim3(NB * NH, NT / 64), 64>>>(pqkv, pa);

        hgemm<false, true, false><<<gD, 128, SM_BYTES>>>(
            pa, pw + OFF_PROJ + (size_t)l * ND * ND,
            bproj + l * ND, px, px, ND, ND);

        ln_kernel<<<MT / 8, 256>>>(px, ln2g + l * ND, ln2b + l * ND, ph);

        hgemm<true, false, true><<<g4, 128, SM_BYTES>>>(
            ph, pw + OFF_W1 + (size_t)l * ND4 * ND,
            b1 + l * ND4, nullptr, pm, ND4, ND);

        hgemm<false, true, false><<<gD, 128, SM_BYTES>>>(
            pm, pw + OFF_W2 + (size_t)l * ND * ND4,
            b2 + l * ND, px, px, ND, ND4);
    }

    ln_kernel<<<MT / 8, 256>>>(px, lnfg, lnfb, ph);
    hgemm<false, false, false><<<gH, 128, SM_BYTES>>>(
        ph, pw + OFF_HEAD, bhead, nullptr, out, NV, ND);
}

// round 7
// speedup vs baseline: 7.4422x; 1.6956x over previous
#include <cuda_runtime.h>
#include <cuda_fp16.h>
#include <cstdint>
#include <math.h>

// ---------------------------------------------------------------------------
// Problem constants
// ---------------------------------------------------------------------------
constexpr int NV  = 65;
constexpr int ND  = 384;
constexpr int NH  = 6;
constexpr int NHD = 64;
constexpr int NL  = 6;
constexpr int NT  = 256;
constexpr int NB  = 64;
constexpr int MT  = NB * NT;       // 16384
constexpr int ND4 = 4 * ND;        // 1536
constexpr int NQKV = 3 * ND;       // 1152

// ---------------------------------------------------------------------------
// Scratch (__device__ globals; allocation-free)
// ---------------------------------------------------------------------------
__device__ float  g_x   [MT * ND];      // fp32 residual stream
__device__ __half g_h16 [MT * ND];      // LN output (GEMM A)
__device__ __half g_qkv [MT * NQKV];    // q|k packed (v region unused)
__device__ __half g_vT  [NB * NH * NHD * NT];  // V transposed per (b,h): [hd][t]
__device__ __half g_att [MT * ND];
__device__ __half g_hid [MT * ND4];

constexpr size_t OFF_QKV  = 0;
constexpr size_t OFF_PROJ = OFF_QKV  + (size_t)NL * NQKV * ND;
constexpr size_t OFF_W1   = OFF_PROJ + (size_t)NL * ND * ND;
constexpr size_t OFF_W2   = OFF_W1   + (size_t)NL * ND4 * ND;
constexpr size_t OFF_HEAD = OFF_W2   + (size_t)NL * ND * ND4;
constexpr size_t WT_TOTAL = OFF_HEAD + (size_t)NV * ND;
__device__ __half g_wT[WT_TOTAL];

// ---------------------------------------------------------------------------
// Helpers
// ---------------------------------------------------------------------------
__device__ __forceinline__ uint32_t smem_u32(const void* p) {
    uint32_t a;
    asm("{ .reg .u64 t; cvta.to.shared.u64 t, %1; cvt.u32.u64 %0, t; }"
        : "=r"(a) : "l"(p));
    return a;
}
__device__ __forceinline__ void cp16(uint32_t dst, const void* src, int srcsize) {
    asm volatile("cp.async.cg.shared.global [%0], [%1], 16, %2;"
                 :: "r"(dst), "l"(src), "r"(srcsize) : "memory");
}
__device__ __forceinline__ void cp_commit() {
    asm volatile("cp.async.commit_group;" ::: "memory");
}
__device__ __forceinline__ void ldm4(uint32_t* r, uint32_t a) {
    asm volatile("ldmatrix.sync.aligned.m8n8.x4.shared.b16 {%0,%1,%2,%3}, [%4];"
                 : "=r"(r[0]), "=r"(r[1]), "=r"(r[2]), "=r"(r[3]) : "r"(a));
}
__device__ __forceinline__ void mma_f16(float* c, const uint32_t* a,
                                        uint32_t b0, uint32_t b1) {
    asm volatile(
        "mma.sync.aligned.m16n8k16.row.col.f32.f16.f16.f32 "
        "{%0,%1,%2,%3}, {%4,%5,%6,%7}, {%8,%9}, {%0,%1,%2,%3};"
        : "+f"(c[0]), "+f"(c[1]), "+f"(c[2]), "+f"(c[3])
        : "r"(a[0]), "r"(a[1]), "r"(a[2]), "r"(a[3]), "r"(b0), "r"(b1));
}
__device__ __forceinline__ uint32_t packh2(float x, float y) {
    __half2 h = __floats2half2_rn(x, y);
    return *reinterpret_cast<uint32_t*>(&h);
}

// ---------------------------------------------------------------------------
// Embedding (fp32 residual stream)
// ---------------------------------------------------------------------------
__global__ void embed_kernel(const int* __restrict__ idx,
                             const float* __restrict__ tok,
                             const float* __restrict__ pos,
                             float* __restrict__ out)
{
    int gid = blockIdx.x * blockDim.x + threadIdx.x;
    int m = gid / ND, d = gid - m * ND;
    out[gid] = tok[(size_t)idx[m] * ND + d] + pos[(m % NT) * ND + d];
}

// ---------------------------------------------------------------------------
// LayerNorm (eps 1e-3), warp-per-row, fp32 in -> fp16 out
// ---------------------------------------------------------------------------
__global__ __launch_bounds__(256) void ln_kernel(const float* __restrict__ x,
                                                 const float* __restrict__ g,
                                                 const float* __restrict__ bb,
                                                 __half* __restrict__ out)
{
    int w = threadIdx.x >> 5, lane = threadIdx.x & 31;
    int row = blockIdx.x * 8 + w;
    const float* xr = x + (size_t)row * ND;

    float4 xv[3];
    float s1 = 0.f, s2 = 0.f;
#pragma unroll
    for (int j = 0; j < 3; j++) {
        float4 v = *(const float4*)(xr + lane * 4 + j * 128);
        xv[j] = v;
        s1 += v.x + v.y + v.z + v.w;
        s2 += v.x * v.x + v.y * v.y + v.z * v.z + v.w * v.w;
    }
#pragma unroll
    for (int o = 16; o > 0; o >>= 1) {
        s1 += __shfl_xor_sync(0xFFFFFFFFu, s1, o);
        s2 += __shfl_xor_sync(0xFFFFFFFFu, s2, o);
    }
    float mean = s1 * (1.f / ND);
    float var  = s2 * (1.f / ND) - mean * mean;
    float rstd = rsqrtf(var + 1e-3f);
#pragma unroll
    for (int j = 0; j < 3; j++) {
        int c = lane * 4 + j * 128;
        float4 gv = *(const float4*)(g + c);
        float4 bv = *(const float4*)(bb + c);
        __half2 h0 = __floats2half2_rn((xv[j].x - mean) * rstd * gv.x + bv.x,
                                       (xv[j].y - mean) * rstd * gv.y + bv.y);
        __half2 h1 = __floats2half2_rn((xv[j].z - mean) * rstd * gv.z + bv.z,
                                       (xv[j].w - mean) * rstd * gv.w + bv.w);
        *(__half2*)(out + (size_t)row * ND + c)     = h0;
        *(__half2*)(out + (size_t)row * ND + c + 2) = h1;
    }
}

// ---------------------------------------------------------------------------
// Tiled transpose: src [R,C] fp32 (+batch offsets) -> dst [C,R] fp16.
// ---------------------------------------------------------------------------
__global__ void transpose_kernel(const float* __restrict__ src,
                                 __half* __restrict__ dst,
                                 int R, int C, int div,
                                 size_t ssA, size_t ssB,
                                 size_t dsA, size_t dsB)
{
    __shared__ float tile[32][33];
    int z = blockIdx.z;
    const float* s = src + (z / div) * ssA + (z % div) * ssB;
    __half* d = dst + (z / div) * dsA + (z % div) * dsB;
    int c0 = blockIdx.x * 32, r0 = blockIdx.y * 32;
#pragma unroll
    for (int j = 0; j < 4; j++) {
        int r = r0 + threadIdx.y + j * 8, c = c0 + threadIdx.x;
        if (r < R && c < C)
            tile[threadIdx.y + j * 8][threadIdx.x] = s[(size_t)r * C + c];
    }
    __syncthreads();
#pragma unroll
    for (int j = 0; j < 4; j++) {
        int c = c0 + threadIdx.y + j * 8, r = r0 + threadIdx.x;
        if (c < C && r < R)
            d[(size_t)c * R + r] = __float2half(tile[threadIdx.x][threadIdx.y + j * 8]);
    }
}

// ---------------------------------------------------------------------------
// fp16 mma.sync GEMM: C[M,N] = A[M,K] * B^T (B [N,K] K-major fp16)
// Tile 128x128x32; 4 warps; warp tile 64x64; 4-stage cp.async ring.
// VSPLIT: for QKV gemm, col blocks >= 768 (the V output) are written
// TRANSPOSED to the vT buffer (passed via 'resid') instead of Cv.
// ---------------------------------------------------------------------------
constexpr int RSH = 40;
constexpr int TILE_H = 128 * RSH;
constexpr int NSTAGE = 4;
constexpr int SM_BYTES = 2 * NSTAGE * TILE_H * 2;  // 81920

template <bool RELU, bool RESID, bool OUTH, bool VSPLIT>
__global__ __launch_bounds__(128) void hgemm(
    const __half* __restrict__ A, const __half* __restrict__ B,
    const float* __restrict__ bias, const float* __restrict__ resid,
    void* __restrict__ Cv, int N, int K)
{
    extern __shared__ __half smh[];
    __shared__ float sbias[128];
    const int tid = threadIdx.x;
    const int row0 = blockIdx.y * 128;
    const int col0 = blockIdx.x * 128;

    uint32_t aAu[NSTAGE], aBu[NSTAGE];
#pragma unroll
    for (int s = 0; s < NSTAGE; s++) {
        aAu[s] = smem_u32(smh + s * TILE_H);
        aBu[s] = smem_u32(smh + (NSTAGE + s) * TILE_H);
    }

    {
        int c = col0 + tid;
        sbias[tid] = (bias && c < N) ? bias[c] : 0.f;
    }

    const int KT = K / 32;

    auto prefetch = [&](int kt, int s) {
#pragma unroll
        for (int i = 0; i < 4; i++) {
            int slot = tid + i * 128;
            int r = slot >> 2, c8 = slot & 3;
            cp16(aAu[s] + (uint32_t)(r * 80 + c8 * 16),
                 A + (size_t)(row0 + r) * K + kt * 32 + c8 * 8, 16);
        }
#pragma unroll
        for (int i = 0; i < 4; i++) {
            int slot = tid + i * 128;
            int r = slot >> 2, c8 = slot & 3;
            int n = col0 + r;
            cp16(aBu[s] + (uint32_t)(r * 80 + c8 * 16),
                 B + (size_t)(n < N ? n : N - 1) * K + kt * 32 + c8 * 8,
                 n < N ? 16 : 0);
        }
        cp_commit();
    };

    const int w = tid >> 5, lane = tid & 31;
    const int wm = (w & 1) * 64;
    const int wn = (w >> 1) * 64;
    const int g = lane >> 2, tg = lane & 3;
    const int lr = lane & 15, lc = (lane >> 4) * 16;

    float acc[4][8][4];
#pragma unroll
    for (int i = 0; i < 4; i++)
#pragma unroll
        for (int j = 0; j < 8; j++)
#pragma unroll
            for (int q = 0; q < 4; q++) acc[i][j][q] = 0.f;

    prefetch(0, 0); prefetch(1, 1); prefetch(2, 2);

    for (int kt = 0; kt < KT; kt++) {
        int rem = KT - 1 - kt;
        if (rem >= 2)      asm volatile("cp.async.wait_group 2;" ::: "memory");
        else if (rem == 1) asm volatile("cp.async.wait_group 1;" ::: "memory");
        else               asm volatile("cp.async.wait_group 0;" ::: "memory");
        __syncthreads();

        if (kt + 3 < KT) prefetch(kt + 3, (kt + 3) & 3);

        uint32_t bA = aAu[kt & 3], bB = aBu[kt & 3];
#pragma unroll
        for (int ks = 0; ks < 2; ks++) {
            uint32_t a[4][4];
#pragma unroll
            for (int i = 0; i < 4; i++)
                ldm4(a[i], bA + (uint32_t)((wm + 16 * i + lr) * 80 + ks * 32 + lc));
            uint32_t b[4][4];
#pragma unroll
            for (int p = 0; p < 4; p++)
                ldm4(b[p], bB + (uint32_t)((wn + 16 * p + lr) * 80 + ks * 32 + lc));
#pragma unroll
            for (int i = 0; i < 4; i++)
#pragma unroll
                for (int p = 0; p < 4; p++) {
                    mma_f16(acc[i][2 * p],     a[i], b[p][0], b[p][2]);
                    mma_f16(acc[i][2 * p + 1], a[i], b[p][1], b[p][3]);
                }
        }
    }

    // Epilogue
    const bool vec = (N & 127) == 0;
    float*  Cf = (float*)Cv;
    __half* Ch = (__half*)Cv;
    __half* vtp = (__half*)resid;   // vT buffer for VSPLIT
#pragma unroll
    for (int i = 0; i < 4; i++) {
#pragma unroll
        for (int half_ = 0; half_ < 2; half_++) {
            int r = row0 + wm + 16 * i + g + 8 * half_;
#pragma unroll
            for (int j = 0; j < 8; j++) {
                int cl = wn + 8 * j + 2 * tg;
                int c = col0 + cl;
                float2 v = { acc[i][j][half_ * 2], acc[i][j][half_ * 2 + 1] };
                v.x += sbias[cl]; v.y += sbias[cl + 1];
                if (RELU) { v.x = fmaxf(v.x, 0.f); v.y = fmaxf(v.y, 0.f); }
                if (OUTH) {
                    if (VSPLIT && col0 >= 2 * ND) {
                        // V output -> transposed store: vT[(b*NH+h)*NHD+hd][t]
                        int cc = c - 2 * ND;
                        int hh = cc >> 6, hd = cc & 63;
                        int bb2 = r >> 8, tt = r & 255;
                        size_t base = ((size_t)(bb2 * NH + hh) * NHD + hd) * NT + tt;
                        vtp[base]      = __float2half(v.x);
                        vtp[base + NT] = __float2half(v.y);
                    } else {
                        *(__half2*)&Ch[(size_t)r * N + c] = __floats2half2_rn(v.x, v.y);
                    }
                } else if (vec) {
                    if (RESID) {
                        float2 rv = *(const float2*)&resid[(size_t)r * N + c];
                        v.x += rv.x; v.y += rv.y;
                    }
                    *(float2*)&Cf[(size_t)r * N + c] = v;
                } else {
                    if (c < N)     Cf[(size_t)r * N + c]     = v.x;
                    if (c + 1 < N) Cf[(size_t)r * N + c + 1] = v.y;
                }
            }
        }
    }
}

// ---------------------------------------------------------------------------
// Flash attention (tensor cores). Block = (b*NH+h, qtile of 64); 4 warps,
// each warp 16 query rows. K tiles of 64 kv; V^T [hd][t] as K-major B.
// fp32 accum + stats; P rounded to fp16.
// ---------------------------------------------------------------------------
constexpr int AST = 72;   // smem halves per row (144 B; ldmatrix conflict-free)

__global__ __launch_bounds__(128) void fattn_kernel(
    const __half* __restrict__ qkv, const __half* __restrict__ vT,
    __half* __restrict__ out)
{
    __shared__ __half sQ[64 * AST], sK[64 * AST], sV[64 * AST];
    const int bh = blockIdx.x, qt = blockIdx.y;
    const int b = bh / NH, h = bh - b * NH;
    const int tid = threadIdx.x, w = tid >> 5, lane = tid & 31;
    const int g = lane >> 2, tg = lane & 3;
    const int lr = lane & 15;
    const uint32_t lc = (lane >> 4) * 16;

    const uint32_t qb = smem_u32(sQ), kb = smem_u32(sK), vb = smem_u32(sV);

    // Load Q tile [64 q][64 hd]
    for (int i = tid; i < 512; i += 128) {
        int r = i >> 3, c8 = i & 7;
        cp16(qb + (uint32_t)(r * AST * 2 + c8 * 16),
             qkv + (size_t)(b * NT + qt * 64 + r) * NQKV + h * NHD + c8 * 8, 16);
    }
    cp_commit();
    asm volatile("cp.async.wait_group 0;" ::: "memory");
    __syncthreads();

    uint32_t qf[4][4];
#pragma unroll
    for (int c = 0; c < 4; c++)
        ldm4(qf[c], qb + (uint32_t)((w * 16 + lr) * AST * 2 + c * 32) + lc);

    float O[8][4];
#pragma unroll
    for (int j = 0; j < 8; j++)
#pragma unroll
        for (int q = 0; q < 4; q++) O[j][q] = 0.f;
    float m0 = -1e30f, m1 = -1e30f, l0 = 0.f, l1 = 0.f;
    const float scale = rsqrtf((float)ND);

    for (int s0 = 0; s0 <= qt * 64; s0 += 64) {
        __syncthreads();   // previous tile's PV done before overwrite
        for (int i = tid; i < 512; i += 128) {
            int r = i >> 3, c8 = i & 7;
            cp16(kb + (uint32_t)(r * AST * 2 + c8 * 16),
                 qkv + (size_t)(b * NT + s0 + r) * NQKV + ND + h * NHD + c8 * 8, 16);
            cp16(vb + (uint32_t)(r * AST * 2 + c8 * 16),
                 vT + ((size_t)bh * NHD + r) * NT + s0 + c8 * 8, 16);
        }
        cp_commit();
        asm volatile("cp.async.wait_group 0;" ::: "memory");
        __syncthreads();

        // S[16 x 64] = Q_w x K^T
        float S[8][4];
#pragma unroll
        for (int j = 0; j < 8; j++)
            S[j][0] = S[j][1] = S[j][2] = S[j][3] = 0.f;
#pragma unroll
        for (int p = 0; p < 4; p++) {
#pragma unroll
            for (int c = 0; c < 4; c++) {
                uint32_t bf[4];
                ldm4(bf, kb + (uint32_t)((p * 16 + lr) * AST * 2 + c * 32) + lc);
                mma_f16(S[2 * p],     qf[c], bf[0], bf[2]);
                mma_f16(S[2 * p + 1], qf[c], bf[1], bf[3]);
            }
        }

        // scale + causal mask (only diagonal tile needs masking)
        const bool diag = (s0 == qt * 64);
        const int r0l = w * 16 + g;
#pragma unroll
        for (int j = 0; j < 8; j++) {
            int cb = j * 8 + 2 * tg;
            S[j][0] *= scale; S[j][1] *= scale;
            S[j][2] *= scale; S[j][3] *= scale;
            if (diag) {
                if (cb     > r0l)     S[j][0] = -1e30f;
                if (cb + 1 > r0l)     S[j][1] = -1e30f;
                if (cb     > r0l + 8) S[j][2] = -1e30f;
                if (cb + 1 > r0l + 8) S[j][3] = -1e30f;
            }
        }

        // online softmax (rows g and g+8; reduce across the 4-lane quad)
        float tm0 = -1e30f, tm1 = -1e30f;
#pragma unroll
        for (int j = 0; j < 8; j++) {
            tm0 = fmaxf(tm0, fmaxf(S[j][0], S[j][1]));
            tm1 = fmaxf(tm1, fmaxf(S[j][2], S[j][3]));
        }
        tm0 = fmaxf(tm0, __shfl_xor_sync(0xFFFFFFFFu, tm0, 1));
        tm0 = fmaxf(tm0, __shfl_xor_sync(0xFFFFFFFFu, tm0, 2));
        tm1 = fmaxf(tm1, __shfl_xor_sync(0xFFFFFFFFu, tm1, 1));
        tm1 = fmaxf(tm1, __shfl_xor_sync(0xFFFFFFFFu, tm1, 2));
        float nm0 = fmaxf(m0, tm0), nm1 = fmaxf(m1, tm1);
        float cor0 = __expf(m0 - nm0), cor1 = __expf(m1 - nm1);
        float ts0 = 0.f, ts1 = 0.f;
#pragma unroll
        for (int j = 0; j < 8; j++) {
            S[j][0] = __expf(S[j][0] - nm0); ts0 += S[j][0];
            S[j][1] = __expf(S[j][1] - nm0); ts0 += S[j][1];
            S[j][2] = __expf(S[j][2] - nm1); ts1 += S[j][2];
            S[j][3] = __expf(S[j][3] - nm1); ts1 += S[j][3];
        }
        ts0 += __shfl_xor_sync(0xFFFFFFFFu, ts0, 1);
        ts0 += __shfl_xor_sync(0xFFFFFFFFu, ts0, 2);
        ts1 += __shfl_xor_sync(0xFFFFFFFFu, ts1, 1);
        ts1 += __shfl_xor_sync(0xFFFFFFFFu, ts1, 2);
        l0 = l0 * cor0 + ts0;  l1 = l1 * cor1 + ts1;
        m0 = nm0;  m1 = nm1;
#pragma unroll
        for (int j = 0; j < 8; j++) {
            O[j][0] *= cor0; O[j][1] *= cor0;
            O[j][2] *= cor1; O[j][3] *= cor1;
        }

        // P fragments (register-local S c-frag -> A-frag)
        uint32_t pf[4][4];
#pragma unroll
        for (int c = 0; c < 4; c++) {
            pf[c][0] = packh2(S[2 * c][0],     S[2 * c][1]);
            pf[c][1] = packh2(S[2 * c][2],     S[2 * c][3]);
            pf[c][2] = packh2(S[2 * c + 1][0], S[2 * c + 1][1]);
            pf[c][3] = packh2(S[2 * c + 1][2], S[2 * c + 1][3]);
        }

        // O += P x V   (B = V^T [hd][kv], K-major in kv)
#pragma unroll
        for (int p = 0; p < 4; p++) {
#pragma unroll
            for (int c = 0; c < 4; c++) {
                uint32_t bf[4];
                ldm4(bf, vb + (uint32_t)((p * 16 + lr) * AST * 2 + c * 32) + lc);
                mma_f16(O[2 * p],     pf[c], bf[0], bf[2]);
                mma_f16(O[2 * p + 1], pf[c], bf[1], bf[3]);
            }
        }
    }

    float i0 = 1.f / l0, i1 = 1.f / l1;
    int qrow = qt * 64 + w * 16 + g;
    size_t ob0 = (size_t)(b * NT + qrow) * ND + h * NHD;
    size_t ob1 = ob0 + (size_t)8 * ND;
#pragma unroll
    for (int j = 0; j < 8; j++) {
        int cc = j * 8 + 2 * tg;
        *(__half2*)(out + ob0 + cc) = __floats2half2_rn(O[j][0] * i0, O[j][1] * i0);
        *(__half2*)(out + ob1 + cc) = __floats2half2_rn(O[j][2] * i1, O[j][3] * i1);
    }
}

// ---------------------------------------------------------------------------
extern "C" void kernel_launch(void* const* d_in, const int* in_sizes, int n_in,
                              void* d_out, int out_size)
{
    const int*   idx   = (const int*)  d_in[0];
    const float* tok   = (const float*)d_in[1];
    const float* pos   = (const float*)d_in[2];
    const float* Wq    = (const float*)d_in[3];
    const float* Wk    = (const float*)d_in[4];
    const float* Wv    = (const float*)d_in[5];
    const float* Wproj = (const float*)d_in[6];
    const float* bproj = (const float*)d_in[7];
    const float* W1    = (const float*)d_in[8];
    const float* b1    = (const float*)d_in[9];
    const float* W2    = (const float*)d_in[10];
    const float* b2    = (const float*)d_in[11];
    const float* ln1g  = (const float*)d_in[12];
    const float* ln1b  = (const float*)d_in[13];
    const float* ln2g  = (const float*)d_in[14];
    const float* ln2b  = (const float*)d_in[15];
    const float* lnfg  = (const float*)d_in[16];
    const float* lnfb  = (const float*)d_in[17];
    const float* Whead = (const float*)d_in[18];
    const float* bhead = (const float*)d_in[19];
    float* out = (float*)d_out;

    float  *px;
    __half *ph, *pqkv, *pvT, *pa, *pm, *pw;
    cudaGetSymbolAddress((void**)&px,   g_x);
    cudaGetSymbolAddress((void**)&ph,   g_h16);
    cudaGetSymbolAddress((void**)&pqkv, g_qkv);
    cudaGetSymbolAddress((void**)&pvT,  g_vT);
    cudaGetSymbolAddress((void**)&pa,   g_att);
    cudaGetSymbolAddress((void**)&pm,   g_hid);
    cudaGetSymbolAddress((void**)&pw,   g_wT);

    static int attr_done = 0;
    if (!attr_done) {
        cudaFuncSetAttribute(hgemm<false, false, true, true>,
                             cudaFuncAttributeMaxDynamicSharedMemorySize, SM_BYTES);
        cudaFuncSetAttribute(hgemm<false, true, false, false>,
                             cudaFuncAttributeMaxDynamicSharedMemorySize, SM_BYTES);
        cudaFuncSetAttribute(hgemm<true, false, true, false>,
                             cudaFuncAttributeMaxDynamicSharedMemorySize, SM_BYTES);
        cudaFuncSetAttribute(hgemm<false, false, false, false>,
                             cudaFuncAttributeMaxDynamicSharedMemorySize, SM_BYTES);
        attr_done = 1;
    }

    // Weight prep: tiled transpose -> K-major [N,K] fp16
    {
        dim3 blk(32, 8);
        dim3 gqv(NHD / 32, ND / 32, NL * NH);
        size_t ssA = (size_t)NH * ND * NHD, ssB = (size_t)ND * NHD;
        size_t dsA = (size_t)NQKV * ND,     dsB = (size_t)NHD * ND;
        transpose_kernel<<<gqv, blk>>>(Wq, pw + OFF_QKV,                       ND, NHD, NH, ssA, ssB, dsA, dsB);
        transpose_kernel<<<gqv, blk>>>(Wk, pw + OFF_QKV + (size_t)ND * ND,     ND, NHD, NH, ssA, ssB, dsA, dsB);
        transpose_kernel<<<gqv, blk>>>(Wv, pw + OFF_QKV + (size_t)2 * ND * ND, ND, NHD, NH, ssA, ssB, dsA, dsB);
        transpose_kernel<<<dim3(ND / 32, ND / 32, NL), blk>>>(
            Wproj, pw + OFF_PROJ, ND, ND, 1, (size_t)ND * ND, 0, (size_t)ND * ND, 0);
        transpose_kernel<<<dim3(ND4 / 32, ND / 32, NL), blk>>>(
            W1, pw + OFF_W1, ND, ND4, 1, (size_t)ND * ND4, 0, (size_t)ND * ND4, 0);
        transpose_kernel<<<dim3(ND / 32, ND4 / 32, NL), blk>>>(
            W2, pw + OFF_W2, ND4, ND, 1, (size_t)ND * ND4, 0, (size_t)ND * ND4, 0);
        transpose_kernel<<<dim3((NV + 31) / 32, ND / 32, 1), blk>>>(
            Whead, pw + OFF_HEAD, ND, NV, 1, 0, 0, 0, 0);
    }

    embed_kernel<<<(MT * ND) / 256, 256>>>(idx, tok, pos, px);

    const int MTILES = MT / 128;
    dim3 gQKV(NQKV / 128, MTILES);
    dim3 gD  (ND   / 128, MTILES);
    dim3 g4  (ND4  / 128, MTILES);
    dim3 gH  (1, MTILES);

    for (int l = 0; l < NL; l++) {
        ln_kernel<<<MT / 8, 256>>>(px, ln1g + l * ND, ln1b + l * ND, ph);

        hgemm<false, false, true, true><<<gQKV, 128, SM_BYTES>>>(
            ph, pw + OFF_QKV + (size_t)l * NQKV * ND,
            nullptr, (const float*)pvT, pqkv, NQKV, ND);

        fattn_kernel<<<dim3(NB * NH, NT / 64), 128>>>(pqkv, pvT, pa);

        hgemm<false, true, false, false><<<gD, 128, SM_BYTES>>>(
            pa, pw + OFF_PROJ + (size_t)l * ND * ND,
            bproj + l * ND, px, px, ND, ND);

        ln_kernel<<<MT / 8, 256>>>(px, ln2g + l * ND, ln2b + l * ND, ph);

        hgemm<true, false, true, false><<<g4, 128, SM_BYTES>>>(
            ph, pw + OFF_W1 + (size_t)l * ND4 * ND,
            b1 + l * ND4, nullptr, pm, ND4, ND);

        hgemm<false, true, false, false><<<gD, 128, SM_BYTES>>>(
            pm, pw + OFF_W2 + (size_t)l * ND * ND4,
            b2 + l * ND, px, px, ND, ND4);
    }

    ln_kernel<<<MT / 8, 256>>>(px, lnfg, lnfb, ph);
    hgemm<false, false, false, false><<<gH, 128, SM_BYTES>>>(
        ph, pw + OFF_HEAD, bhead, nullptr, out, NV, ND);
}

// round 8
// speedup vs baseline: 7.4773x; 1.0047x over previous
#include <cuda_runtime.h>
#include <cuda_fp16.h>
#include <cstdint>
#include <math.h>

// ---------------------------------------------------------------------------
// Problem constants
// ---------------------------------------------------------------------------
constexpr int NV  = 65;
constexpr int ND  = 384;
constexpr int NH  = 6;
constexpr int NHD = 64;
constexpr int NL  = 6;
constexpr int NT  = 256;
constexpr int NB  = 64;
constexpr int MT  = NB * NT;       // 16384
constexpr int ND4 = 4 * ND;        // 1536
constexpr int NQKV = 3 * ND;       // 1152

// ---------------------------------------------------------------------------
// Scratch (__device__ globals; allocation-free)
// ---------------------------------------------------------------------------
__device__ float  g_x   [MT * ND];      // fp32 residual stream
__device__ __half g_h16 [MT * ND];      // LN output (GEMM A)
__device__ __half g_qkv [MT * NQKV];    // q|k packed (v region unused)
__device__ __half g_vT  [NB * NH * NHD * NT];  // V transposed per (b,h): [hd][t]
__device__ __half g_att [MT * ND];
__device__ __half g_hid [MT * ND4];

constexpr size_t OFF_QKV  = 0;
constexpr size_t OFF_PROJ = OFF_QKV  + (size_t)NL * NQKV * ND;
constexpr size_t OFF_W1   = OFF_PROJ + (size_t)NL * ND * ND;
constexpr size_t OFF_W2   = OFF_W1   + (size_t)NL * ND4 * ND;
constexpr size_t OFF_HEAD = OFF_W2   + (size_t)NL * ND * ND4;
constexpr size_t WT_TOTAL = OFF_HEAD + (size_t)NV * ND;
__device__ __half g_wT[WT_TOTAL];

// ---------------------------------------------------------------------------
// Helpers
// ---------------------------------------------------------------------------
__device__ __forceinline__ uint32_t smem_u32(const void* p) {
    uint32_t a;
    asm("{ .reg .u64 t; cvta.to.shared.u64 t, %1; cvt.u32.u64 %0, t; }"
        : "=r"(a) : "l"(p));
    return a;
}
__device__ __forceinline__ void cp16(uint32_t dst, const void* src, int srcsize) {
    asm volatile("cp.async.cg.shared.global [%0], [%1], 16, %2;"
                 :: "r"(dst), "l"(src), "r"(srcsize) : "memory");
}
__device__ __forceinline__ void cp_commit() {
    asm volatile("cp.async.commit_group;" ::: "memory");
}
__device__ __forceinline__ void ldm4(uint32_t* r, uint32_t a) {
    asm volatile("ldmatrix.sync.aligned.m8n8.x4.shared.b16 {%0,%1,%2,%3}, [%4];"
                 : "=r"(r[0]), "=r"(r[1]), "=r"(r[2]), "=r"(r[3]) : "r"(a));
}
__device__ __forceinline__ void mma_f16(float* c, const uint32_t* a,
                                        uint32_t b0, uint32_t b1) {
    asm volatile(
        "mma.sync.aligned.m16n8k16.row.col.f32.f16.f16.f32 "
        "{%0,%1,%2,%3}, {%4,%5,%6,%7}, {%8,%9}, {%0,%1,%2,%3};"
        : "+f"(c[0]), "+f"(c[1]), "+f"(c[2]), "+f"(c[3])
        : "r"(a[0]), "r"(a[1]), "r"(a[2]), "r"(a[3]), "r"(b0), "r"(b1));
}
__device__ __forceinline__ uint32_t packh2(float x, float y) {
    __half2 h = __floats2half2_rn(x, y);
    return *reinterpret_cast<uint32_t*>(&h);
}

// ---------------------------------------------------------------------------
// Embedding (fp32 residual stream)
// ---------------------------------------------------------------------------
__global__ void embed_kernel(const int* __restrict__ idx,
                             const float* __restrict__ tok,
                             const float* __restrict__ pos,
                             float* __restrict__ out)
{
    int gid = blockIdx.x * blockDim.x + threadIdx.x;
    int m = gid / ND, d = gid - m * ND;
    out[gid] = tok[(size_t)idx[m] * ND + d] + pos[(m % NT) * ND + d];
}

// ---------------------------------------------------------------------------
// LayerNorm (eps 1e-3), warp-per-row, fp32 in -> fp16 out
// ---------------------------------------------------------------------------
__global__ __launch_bounds__(256) void ln_kernel(const float* __restrict__ x,
                                                 const float* __restrict__ g,
                                                 const float* __restrict__ bb,
                                                 __half* __restrict__ out)
{
    int w = threadIdx.x >> 5, lane = threadIdx.x & 31;
    int row = blockIdx.x * 8 + w;
    const float* xr = x + (size_t)row * ND;

    float4 xv[3];
    float s1 = 0.f, s2 = 0.f;
#pragma unroll
    for (int j = 0; j < 3; j++) {
        float4 v = *(const float4*)(xr + lane * 4 + j * 128);
        xv[j] = v;
        s1 += v.x + v.y + v.z + v.w;
        s2 += v.x * v.x + v.y * v.y + v.z * v.z + v.w * v.w;
    }
#pragma unroll
    for (int o = 16; o > 0; o >>= 1) {
        s1 += __shfl_xor_sync(0xFFFFFFFFu, s1, o);
        s2 += __shfl_xor_sync(0xFFFFFFFFu, s2, o);
    }
    float mean = s1 * (1.f / ND);
    float var  = s2 * (1.f / ND) - mean * mean;
    float rstd = rsqrtf(var + 1e-3f);
#pragma unroll
    for (int j = 0; j < 3; j++) {
        int c = lane * 4 + j * 128;
        float4 gv = *(const float4*)(g + c);
        float4 bv = *(const float4*)(bb + c);
        __half2 h0 = __floats2half2_rn((xv[j].x - mean) * rstd * gv.x + bv.x,
                                       (xv[j].y - mean) * rstd * gv.y + bv.y);
        __half2 h1 = __floats2half2_rn((xv[j].z - mean) * rstd * gv.z + bv.z,
                                       (xv[j].w - mean) * rstd * gv.w + bv.w);
        *(__half2*)(out + (size_t)row * ND + c)     = h0;
        *(__half2*)(out + (size_t)row * ND + c + 2) = h1;
    }
}

// ---------------------------------------------------------------------------
// Tiled transpose: src [R,C] fp32 (+batch offsets) -> dst [C,R] fp16.
// ---------------------------------------------------------------------------
__global__ void transpose_kernel(const float* __restrict__ src,
                                 __half* __restrict__ dst,
                                 int R, int C, int div,
                                 size_t ssA, size_t ssB,
                                 size_t dsA, size_t dsB)
{
    __shared__ float tile[32][33];
    int z = blockIdx.z;
    const float* s = src + (z / div) * ssA + (z % div) * ssB;
    __half* d = dst + (z / div) * dsA + (z % div) * dsB;
    int c0 = blockIdx.x * 32, r0 = blockIdx.y * 32;
#pragma unroll
    for (int j = 0; j < 4; j++) {
        int r = r0 + threadIdx.y + j * 8, c = c0 + threadIdx.x;
        if (r < R && c < C)
            tile[threadIdx.y + j * 8][threadIdx.x] = s[(size_t)r * C + c];
    }
    __syncthreads();
#pragma unroll
    for (int j = 0; j < 4; j++) {
        int c = c0 + threadIdx.y + j * 8, r = r0 + threadIdx.x;
        if (c < C && r < R)
            d[(size_t)c * R + r] = __float2half(tile[threadIdx.x][threadIdx.y + j * 8]);
    }
}

// ---------------------------------------------------------------------------
// fp16 mma.sync GEMM, templated block-M:
//   BM=128: 4 warps of 64x64 (8 warps/SM), used for big-N GEMMs.
//   BM=64 : 4 warps of 32x64 (3 blocks/SM = 12 warps), kills wave tails
//           on the N=384 GEMMs (proj, W2).
// B is [N,K] K-major fp16; 4-stage cp.async ring; rows padded to 80B.
// VSPLIT (BM=128 only): QKV col blocks >= 768 stored transposed to vT.
// ---------------------------------------------------------------------------
constexpr int NSTAGE = 4;
constexpr int smbytes(int BM) { return NSTAGE * (BM + 128) * 80; }

template <int BM, bool RELU, bool RESID, bool OUTH, bool VSPLIT>
__global__ __launch_bounds__(128, BM == 64 ? 3 : 1) void hgemm(
    const __half* __restrict__ A, const __half* __restrict__ B,
    const float* __restrict__ bias, const float* __restrict__ resid,
    void* __restrict__ Cv, int N, int K)
{
    constexpr int AF = BM / 32;            // A fragments per warp
    extern __shared__ __half smh[];
    __shared__ float sbias[128];
    const int tid = threadIdx.x;
    const int row0 = blockIdx.y * BM;
    const int col0 = blockIdx.x * 128;

    const uint32_t base = smem_u32(smh);
    uint32_t aAu[NSTAGE], aBu[NSTAGE];
#pragma unroll
    for (int s = 0; s < NSTAGE; s++) {
        aAu[s] = base + s * BM * 80;
        aBu[s] = base + NSTAGE * BM * 80 + s * 128 * 80;
    }

    {
        int c = col0 + tid;
        sbias[tid] = (bias && c < N) ? bias[c] : 0.f;
    }

    const int KT = K / 32;

    auto prefetch = [&](int kt, int s) {
#pragma unroll
        for (int i = 0; i < BM / 32; i++) {
            int slot = tid + i * 128;
            int r = slot >> 2, c8 = slot & 3;
            cp16(aAu[s] + (uint32_t)(r * 80 + c8 * 16),
                 A + (size_t)(row0 + r) * K + kt * 32 + c8 * 8, 16);
        }
#pragma unroll
        for (int i = 0; i < 4; i++) {
            int slot = tid + i * 128;
            int r = slot >> 2, c8 = slot & 3;
            int n = col0 + r;
            cp16(aBu[s] + (uint32_t)(r * 80 + c8 * 16),
                 B + (size_t)(n < N ? n : N - 1) * K + kt * 32 + c8 * 8,
                 n < N ? 16 : 0);
        }
        cp_commit();
    };

    const int w = tid >> 5, lane = tid & 31;
    const int wm = (w & 1) * (BM / 2);
    const int wn = (w >> 1) * 64;
    const int g = lane >> 2, tg = lane & 3;
    const int lr = lane & 15, lc = (lane >> 4) * 16;

    float acc[AF][8][4];
#pragma unroll
    for (int i = 0; i < AF; i++)
#pragma unroll
        for (int j = 0; j < 8; j++)
#pragma unroll
            for (int q = 0; q < 4; q++) acc[i][j][q] = 0.f;

    prefetch(0, 0); prefetch(1, 1); prefetch(2, 2);

    for (int kt = 0; kt < KT; kt++) {
        int rem = KT - 1 - kt;
        if (rem >= 2)      asm volatile("cp.async.wait_group 2;" ::: "memory");
        else if (rem == 1) asm volatile("cp.async.wait_group 1;" ::: "memory");
        else               asm volatile("cp.async.wait_group 0;" ::: "memory");
        __syncthreads();

        if (kt + 3 < KT) prefetch(kt + 3, (kt + 3) & 3);

        uint32_t bA = aAu[kt & 3], bB = aBu[kt & 3];
#pragma unroll
        for (int ks = 0; ks < 2; ks++) {
            uint32_t a[AF][4];
#pragma unroll
            for (int i = 0; i < AF; i++)
                ldm4(a[i], bA + (uint32_t)((wm + 16 * i + lr) * 80 + ks * 32 + lc));
            uint32_t b[4][4];
#pragma unroll
            for (int p = 0; p < 4; p++)
                ldm4(b[p], bB + (uint32_t)((wn + 16 * p + lr) * 80 + ks * 32 + lc));
#pragma unroll
            for (int i = 0; i < AF; i++)
#pragma unroll
                for (int p = 0; p < 4; p++) {
                    mma_f16(acc[i][2 * p],     a[i], b[p][0], b[p][2]);
                    mma_f16(acc[i][2 * p + 1], a[i], b[p][1], b[p][3]);
                }
        }
    }

    // Epilogue
    const bool vec = (N & 127) == 0;
    float*  Cf = (float*)Cv;
    __half* Ch = (__half*)Cv;
    __half* vtp = (__half*)resid;   // vT buffer for VSPLIT
#pragma unroll
    for (int i = 0; i < AF; i++) {
#pragma unroll
        for (int half_ = 0; half_ < 2; half_++) {
            int r = row0 + wm + 16 * i + g + 8 * half_;
#pragma unroll
            for (int j = 0; j < 8; j++) {
                int cl = wn + 8 * j + 2 * tg;
                int c = col0 + cl;
                float2 v = { acc[i][j][half_ * 2], acc[i][j][half_ * 2 + 1] };
                v.x += sbias[cl]; v.y += sbias[cl + 1];
                if (RELU) { v.x = fmaxf(v.x, 0.f); v.y = fmaxf(v.y, 0.f); }
                if (OUTH) {
                    if (VSPLIT && col0 >= 2 * ND) {
                        int cc = c - 2 * ND;
                        int hh = cc >> 6, hd = cc & 63;
                        int bb2 = r >> 8, tt = r & 255;
                        size_t vbse = ((size_t)(bb2 * NH + hh) * NHD + hd) * NT + tt;
                        vtp[vbse]      = __float2half(v.x);
                        vtp[vbse + NT] = __float2half(v.y);
                    } else {
                        *(__half2*)&Ch[(size_t)r * N + c] = __floats2half2_rn(v.x, v.y);
                    }
                } else if (vec) {
                    if (RESID) {
                        float2 rv = *(const float2*)&resid[(size_t)r * N + c];
                        v.x += rv.x; v.y += rv.y;
                    }
                    *(float2*)&Cf[(size_t)r * N + c] = v;
                } else {
                    if (c < N)     Cf[(size_t)r * N + c]     = v.x;
                    if (c + 1 < N) Cf[(size_t)r * N + c + 1] = v.y;
                }
            }
        }
    }
}

// ---------------------------------------------------------------------------
// Flash attention (tensor cores). Block = (b*NH+h, qtile of 128); 8 warps,
// each warp 16 query rows. K/V tiles of 64 kv; V^T [hd][t] as K-major B.
// Fully-masked warps skip compute (exact). fp32 accum + stats.
// ---------------------------------------------------------------------------
constexpr int AST = 72;   // smem halves per row (144 B)

__global__ __launch_bounds__(256) void fattn_kernel(
    const __half* __restrict__ qkv, const __half* __restrict__ vT,
    __half* __restrict__ out)
{
    __shared__ __half sQ[128 * AST], sK[64 * AST], sV[64 * AST];
    const int bh = blockIdx.x, qt = blockIdx.y;
    const int b = bh / NH, h = bh - b * NH;
    const int tid = threadIdx.x, w = tid >> 5, lane = tid & 31;
    const int g = lane >> 2, tg = lane & 3;
    const int lr = lane & 15;
    const uint32_t lc = (lane >> 4) * 16;

    const uint32_t qb = smem_u32(sQ), kb = smem_u32(sK), vb = smem_u32(sV);

    // Load Q tile [128 q][64 hd]
    for (int i = tid; i < 1024; i += 256) {
        int r = i >> 3, c8 = i & 7;
        cp16(qb + (uint32_t)(r * AST * 2 + c8 * 16),
             qkv + (size_t)(b * NT + qt * 128 + r) * NQKV + h * NHD + c8 * 8, 16);
    }
    cp_commit();
    asm volatile("cp.async.wait_group 0;" ::: "memory");
    __syncthreads();

    uint32_t qf[4][4];
#pragma unroll
    for (int c = 0; c < 4; c++)
        ldm4(qf[c], qb + (uint32_t)((w * 16 + lr) * AST * 2 + c * 32) + lc);

    float O[8][4];
#pragma unroll
    for (int j = 0; j < 8; j++)
#pragma unroll
        for (int q = 0; q < 4; q++) O[j][q] = 0.f;
    float m0 = -1e30f, m1 = -1e30f, l0 = 0.f, l1 = 0.f;
    const float scale = rsqrtf((float)ND);

    const int wrow = qt * 128 + w * 16;   // warp's first global query row
    const int smax = qt * 128 + 64;       // last kv tile start

    for (int s0 = 0; s0 <= smax; s0 += 64) {
        __syncthreads();   // previous tile's PV done before overwrite
        for (int i = tid; i < 512; i += 256) {
            int r = i >> 3, c8 = i & 7;
            cp16(kb + (uint32_t)(r * AST * 2 + c8 * 16),
                 qkv + (size_t)(b * NT + s0 + r) * NQKV + ND + h * NHD + c8 * 8, 16);
            cp16(vb + (uint32_t)(r * AST * 2 + c8 * 16),
                 vT + ((size_t)bh * NHD + r) * NT + s0 + c8 * 8, 16);
        }
        cp_commit();
        asm volatile("cp.async.wait_group 0;" ::: "memory");
        __syncthreads();

        if (s0 > wrow + 15) continue;   // warp fully masked: exact zero contrib

        // S[16 x 64] = Q_w x K^T
        float S[8][4];
#pragma unroll
        for (int j = 0; j < 8; j++)
            S[j][0] = S[j][1] = S[j][2] = S[j][3] = 0.f;
#pragma unroll
        for (int p = 0; p < 4; p++) {
#pragma unroll
            for (int c = 0; c < 4; c++) {
                uint32_t bf[4];
                ldm4(bf, kb + (uint32_t)((p * 16 + lr) * AST * 2 + c * 32) + lc);
                mma_f16(S[2 * p],     qf[c], bf[0], bf[2]);
                mma_f16(S[2 * p + 1], qf[c], bf[1], bf[3]);
            }
        }

        // scale + causal mask (global indices)
        const bool diag = (s0 + 63 > wrow);
        const int rg0 = wrow + g, rg1 = wrow + g + 8;
#pragma unroll
        for (int j = 0; j < 8; j++) {
            int cg = s0 + j * 8 + 2 * tg;
            S[j][0] *= scale; S[j][1] *= scale;
            S[j][2] *= scale; S[j][3] *= scale;
            if (diag) {
                if (cg     > rg0) S[j][0] = -1e30f;
                if (cg + 1 > rg0) S[j][1] = -1e30f;
                if (cg     > rg1) S[j][2] = -1e30f;
                if (cg + 1 > rg1) S[j][3] = -1e30f;
            }
        }

        // online softmax (rows g and g+8; reduce across 4-lane quad)
        float tm0 = -1e30f, tm1 = -1e30f;
#pragma unroll
        for (int j = 0; j < 8; j++) {
            tm0 = fmaxf(tm0, fmaxf(S[j][0], S[j][1]));
            tm1 = fmaxf(tm1, fmaxf(S[j][2], S[j][3]));
        }
        tm0 = fmaxf(tm0, __shfl_xor_sync(0xFFFFFFFFu, tm0, 1));
        tm0 = fmaxf(tm0, __shfl_xor_sync(0xFFFFFFFFu, tm0, 2));
        tm1 = fmaxf(tm1, __shfl_xor_sync(0xFFFFFFFFu, tm1, 1));
        tm1 = fmaxf(tm1, __shfl_xor_sync(0xFFFFFFFFu, tm1, 2));
        float nm0 = fmaxf(m0, tm0), nm1 = fmaxf(m1, tm1);
        float cor0 = __expf(m0 - nm0), cor1 = __expf(m1 - nm1);
        float ts0 = 0.f, ts1 = 0.f;
#pragma unroll
        for (int j = 0; j < 8; j++) {
            S[j][0] = __expf(S[j][0] - nm0); ts0 += S[j][0];
            S[j][1] = __expf(S[j][1] - nm0); ts0 += S[j][1];
            S[j][2] = __expf(S[j][2] - nm1); ts1 += S[j][2];
            S[j][3] = __expf(S[j][3] - nm1); ts1 += S[j][3];
        }
        ts0 += __shfl_xor_sync(0xFFFFFFFFu, ts0, 1);
        ts0 += __shfl_xor_sync(0xFFFFFFFFu, ts0, 2);
        ts1 += __shfl_xor_sync(0xFFFFFFFFu, ts1, 1);
        ts1 += __shfl_xor_sync(0xFFFFFFFFu, ts1, 2);
        l0 = l0 * cor0 + ts0;  l1 = l1 * cor1 + ts1;
        m0 = nm0;  m1 = nm1;
#pragma unroll
        for (int j = 0; j < 8; j++) {
            O[j][0] *= cor0; O[j][1] *= cor0;
            O[j][2] *= cor1; O[j][3] *= cor1;
        }

        // P fragments (register-local)
        uint32_t pf[4][4];
#pragma unroll
        for (int c = 0; c < 4; c++) {
            pf[c][0] = packh2(S[2 * c][0],     S[2 * c][1]);
            pf[c][1] = packh2(S[2 * c][2],     S[2 * c][3]);
            pf[c][2] = packh2(S[2 * c + 1][0], S[2 * c + 1][1]);
            pf[c][3] = packh2(S[2 * c + 1][2], S[2 * c + 1][3]);
        }

        // O += P x V
#pragma unroll
        for (int p = 0; p < 4; p++) {
#pragma unroll
            for (int c = 0; c < 4; c++) {
                uint32_t bf[4];
                ldm4(bf, vb + (uint32_t)((p * 16 + lr) * AST * 2 + c * 32) + lc);
                mma_f16(O[2 * p],     pf[c], bf[0], bf[2]);
                mma_f16(O[2 * p + 1], pf[c], bf[1], bf[3]);
            }
        }
    }

    float i0 = 1.f / l0, i1 = 1.f / l1;
    int qrow = qt * 128 + w * 16 + g;
    size_t ob0 = (size_t)(b * NT + qrow) * ND + h * NHD;
    size_t ob1 = ob0 + (size_t)8 * ND;
#pragma unroll
    for (int j = 0; j < 8; j++) {
        int cc = j * 8 + 2 * tg;
        *(__half2*)(out + ob0 + cc) = __floats2half2_rn(O[j][0] * i0, O[j][1] * i0);
        *(__half2*)(out + ob1 + cc) = __floats2half2_rn(O[j][2] * i1, O[j][3] * i1);
    }
}

// ---------------------------------------------------------------------------
extern "C" void kernel_launch(void* const* d_in, const int* in_sizes, int n_in,
                              void* d_out, int out_size)
{
    const int*   idx   = (const int*)  d_in[0];
    const float* tok   = (const float*)d_in[1];
    const float* pos   = (const float*)d_in[2];
    const float* Wq    = (const float*)d_in[3];
    const float* Wk    = (const float*)d_in[4];
    const float* Wv    = (const float*)d_in[5];
    const float* Wproj = (const float*)d_in[6];
    const float* bproj = (const float*)d_in[7];
    const float* W1    = (const float*)d_in[8];
    const float* b1    = (const float*)d_in[9];
    const float* W2    = (const float*)d_in[10];
    const float* b2    = (const float*)d_in[11];
    const float* ln1g  = (const float*)d_in[12];
    const float* ln1b  = (const float*)d_in[13];
    const float* ln2g  = (const float*)d_in[14];
    const float* ln2b  = (const float*)d_in[15];
    const float* lnfg  = (const float*)d_in[16];
    const float* lnfb  = (const float*)d_in[17];
    const float* Whead = (const float*)d_in[18];
    const float* bhead = (const float*)d_in[19];
    float* out = (float*)d_out;

    float  *px;
    __half *ph, *pqkv, *pvT, *pa, *pm, *pw;
    cudaGetSymbolAddress((void**)&px,   g_x);
    cudaGetSymbolAddress((void**)&ph,   g_h16);
    cudaGetSymbolAddress((void**)&pqkv, g_qkv);
    cudaGetSymbolAddress((void**)&pvT,  g_vT);
    cudaGetSymbolAddress((void**)&pa,   g_att);
    cudaGetSymbolAddress((void**)&pm,   g_hid);
    cudaGetSymbolAddress((void**)&pw,   g_wT);

    static int attr_done = 0;
    if (!attr_done) {
        cudaFuncSetAttribute(hgemm<128, false, false, true, true>,
                             cudaFuncAttributeMaxDynamicSharedMemorySize, smbytes(128));
        cudaFuncSetAttribute(hgemm<64, false, true, false, false>,
                             cudaFuncAttributeMaxDynamicSharedMemorySize, smbytes(64));
        cudaFuncSetAttribute(hgemm<128, true, false, true, false>,
                             cudaFuncAttributeMaxDynamicSharedMemorySize, smbytes(128));
        cudaFuncSetAttribute(hgemm<128, false, false, false, false>,
                             cudaFuncAttributeMaxDynamicSharedMemorySize, smbytes(128));
        attr_done = 1;
    }

    // Weight prep: tiled transpose -> K-major [N,K] fp16
    {
        dim3 blk(32, 8);
        dim3 gqv(NHD / 32, ND / 32, NL * NH);
        size_t ssA = (size_t)NH * ND * NHD, ssB = (size_t)ND * NHD;
        size_t dsA = (size_t)NQKV * ND,     dsB = (size_t)NHD * ND;
        transpose_kernel<<<gqv, blk>>>(Wq, pw + OFF_QKV,                       ND, NHD, NH, ssA, ssB, dsA, dsB);
        transpose_kernel<<<gqv, blk>>>(Wk, pw + OFF_QKV + (size_t)ND * ND,     ND, NHD, NH, ssA, ssB, dsA, dsB);
        transpose_kernel<<<gqv, blk>>>(Wv, pw + OFF_QKV + (size_t)2 * ND * ND, ND, NHD, NH, ssA, ssB, dsA, dsB);
        transpose_kernel<<<dim3(ND / 32, ND / 32, NL), blk>>>(
            Wproj, pw + OFF_PROJ, ND, ND, 1, (size_t)ND * ND, 0, (size_t)ND * ND, 0);
        transpose_kernel<<<dim3(ND4 / 32, ND / 32, NL), blk>>>(
            W1, pw + OFF_W1, ND, ND4, 1, (size_t)ND * ND4, 0, (size_t)ND * ND4, 0);
        transpose_kernel<<<dim3(ND / 32, ND4 / 32, NL), blk>>>(
            W2, pw + OFF_W2, ND4, ND, 1, (size_t)ND * ND4, 0, (size_t)ND * ND4, 0);
        transpose_kernel<<<dim3((NV + 31) / 32, ND / 32, 1), blk>>>(
            Whead, pw + OFF_HEAD, ND, NV, 1, 0, 0, 0, 0);
    }

    embed_kernel<<<(MT * ND) / 256, 256>>>(idx, tok, pos, px);

    dim3 gQKV(NQKV / 128, MT / 128);
    dim3 gP  (ND   / 128, MT / 64);     // BM=64 grids (proj, W2)
    dim3 g4  (ND4  / 128, MT / 128);
    dim3 gH  (1, MT / 128);

    for (int l = 0; l < NL; l++) {
        ln_kernel<<<MT / 8, 256>>>(px, ln1g + l * ND, ln1b + l * ND, ph);

        hgemm<128, false, false, true, true><<<gQKV, 128, smbytes(128)>>>(
            ph, pw + OFF_QKV + (size_t)l * NQKV * ND,
            nullptr, (const float*)pvT, pqkv, NQKV, ND);

        fattn_kernel<<<dim3(NB * NH, NT / 128), 256>>>(pqkv, pvT, pa);

        hgemm<64, false, true, false, false><<<gP, 128, smbytes(64)>>>(
            pa, pw + OFF_PROJ + (size_t)l * ND * ND,
            bproj + l * ND, px, px, ND, ND);

        ln_kernel<<<MT / 8, 256>>>(px, ln2g + l * ND, ln2b + l * ND, ph);

        hgemm<128, true, false, true, false><<<g4, 128, smbytes(128)>>>(
            ph, pw + OFF_W1 + (size_t)l * ND4 * ND,
            b1 + l * ND4, nullptr, pm, ND4, ND);

        hgemm<64, false, true, false, false><<<gP, 128, smbytes(64)>>>(
            pm, pw + OFF_W2 + (size_t)l * ND * ND4,
            b2 + l * ND, px, px, ND, ND4);
    }

    ln_kernel<<<MT / 8, 256>>>(px, lnfg, lnfb, ph);
    hgemm<128, false, false, false, false><<<gH, 128, smbytes(128)>>>(
        ph, pw + OFF_HEAD, bhead, nullptr, out, NV, ND);
}